// round 3
// baseline (speedup 1.0000x reference)
#include <cuda_runtime.h>
#include <math.h>
#include <stdint.h>

#define Bn 8
#define Ln 64
#define Dn 256
#define Kn 32

// Scratch (device globals -- allocation is forbidden)
__device__ float g_A1d[Bn*Ln*Kn];
__device__ float g_A1g[Bn*Ln*Kn];
__device__ float g_A2d[Bn*Ln*Kn];
__device__ float g_A2g[Bn*Ln*Kn];
__device__ float g_T[(size_t)Bn*Kn*Ln*Dn];   // 16 MB: T[b,k,m,f]
__device__ float g_S[Bn*Kn*Ln*Ln];           // 4 MB: per-k scaled contributions

// ---- K0: projections. one thread per (b,r,k). idx = (b*64+r)*32 + k ----
__global__ void proj_simple(const float* __restrict__ arg1, const float* __restrict__ arg2,
                            const float* __restrict__ Wd, const float* __restrict__ Wg){
    int idx = blockIdx.x*blockDim.x + threadIdx.x;   // 0..16383
    int k = idx & 31;
    const float* a1 = arg1 + (idx>>5)*Dn;            // row (b*64+r)
    const float* a2 = arg2 + (idx>>5)*Dn;
    float s1d=0.f, s1g=0.f, s2d=0.f, s2g=0.f;
    for(int e=0;e<Dn;e++){
        float x1=a1[e], x2=a2[e];
        s1d = fmaf(x1, Wd[e*Kn+k],      s1d);
        s1g = fmaf(x1, Wg[e*Kn+k],      s1g);
        s2d = fmaf(x2, Wd[(Dn+e)*Kn+k], s2d);
        s2g = fmaf(x2, Wg[(Dn+e)*Kn+k], s2g);
    }
    g_A1d[idx]=s1d; g_A1g[idx]=s1g; g_A2d[idx]=s2d; g_A2g[idx]=s2g;
}

// ---- K1: T[b,k,m,f] = sum_e arg1[b,m,e]*Wb[k,e,f]. block=(b,k), thread=f ----
__global__ void __launch_bounds__(256) t_kernel(const float* __restrict__ arg1,
                                                const float* __restrict__ Wb){
    extern __shared__ float a_sh[];                  // 64*256 floats
    int b = blockIdx.x >> 5, k = blockIdx.x & 31;
    int tid = threadIdx.x;                           // f = tid
    const float* A1 = arg1 + b*Ln*Dn;
    for(int i=tid;i<Ln*Dn;i+=256) a_sh[i]=A1[i];
    __syncthreads();
    const float* Wk = Wb + (size_t)k*Dn*Dn;
    float acc[Ln];
    #pragma unroll
    for(int m=0;m<Ln;m++) acc[m]=0.f;
    for(int e=0;e<Dn;e++){
        float w = Wk[e*Dn + tid];                    // coalesced over tid
        #pragma unroll
        for(int m=0;m<Ln;m++)
            acc[m] = fmaf(a_sh[m*Dn+e], w, acc[m]);  // broadcast LDS
    }
    float* Tb = g_T + (size_t)(b*Kn+k)*Ln*Dn;
    #pragma unroll
    for(int m=0;m<Ln;m++) Tb[m*Dn+tid] = acc[m];
}

// ---- K2: btp[b,k,m,n] = sum_f T[b,k,m,f]*arg2[b,n,f], + epilogue ----
#define PAD 257
__global__ void __launch_bounds__(256) btp_kernel(const float* __restrict__ arg2,
        const float* __restrict__ bgp, const float* __restrict__ bp,
        const float* __restrict__ up){
    extern __shared__ float sh[];
    float* T_sh  = sh;             // [64][257]
    float* A2_sh = sh + Ln*PAD;    // [64][257]
    int b = blockIdx.x >> 5, k = blockIdx.x & 31;
    int tid = threadIdx.x;
    const float* Tb = g_T + (size_t)(b*Kn+k)*Ln*Dn;
    const float* A2 = arg2 + b*Ln*Dn;
    for(int i=tid;i<Ln*Dn;i+=256){
        int r=i>>8, c=i&255;
        T_sh [r*PAD+c]=Tb[i];
        A2_sh[r*PAD+c]=A2[i];
    }
    __syncthreads();
    int n = tid & 63, mg = tid >> 6;                 // thread owns m = mg+4*i
    float acc[16];
    #pragma unroll
    for(int i=0;i<16;i++) acc[i]=0.f;
    for(int f=0;f<Dn;f++){
        float av = A2_sh[n*PAD+f];                   // conflict-free (odd stride)
        #pragma unroll
        for(int i=0;i<16;i++)
            acc[i] = fmaf(T_sh[(mg+4*i)*PAD+f], av, acc[i]);  // broadcast
    }
    float bgk=bgp[k], bk=bp[k], uk=up[k];
    float a2d_v = g_A2d[(b*Ln+n)*Kn+k];
    float a2g_v = g_A2g[(b*Ln+n)*Kn+k];
    float* Sb = g_S + (size_t)(b*Kn+k)*Ln*Ln;
    #pragma unroll
    for(int i=0;i<16;i++){
        int m = mg + 4*i;
        float a1d_v = g_A1d[(b*Ln+m)*Kn+k];
        float a1g_v = g_A1g[(b*Ln+m)*Kn+k];
        float sln = tanhf(a1d_v + a2d_v);
        float xg  = a1g_v + a2g_v + bgk;
        float gt  = 1.0f/(1.0f+expf(-xg));
        Sb[m*Ln+n] = uk*(gt*acc[i] + (1.0f-gt)*sln + bk);
    }
}

// ---- K3: deterministic k-reduction ----
__global__ void reduce_kernel(float* __restrict__ out){
    int idx = blockIdx.x*blockDim.x + threadIdx.x;   // 32768
    int b = idx >> 12, mn = idx & 4095;
    const float* s = g_S + (size_t)b*Kn*4096 + mn;
    float acc = 0.f;
    #pragma unroll
    for(int kk=0; kk<Kn; kk++) acc += s[kk*4096];
    out[idx] = acc;
}

extern "C" void kernel_launch(void* const* d_in, const int* in_sizes, int n_in,
                              void* d_out, int out_size){
    // Defensive size-based input identification (robust to metadata ordering).
    const float *arg1=0,*arg2=0,*Wb=0,*Wd=0,*Wg=0,*bg=0,*bb=0,*u=0;
    int nBig=0, nMed=0, nSmall=0;
    for(int i=0;i<n_in;i++){
        int sz = in_sizes[i];
        const float* p = (const float*)d_in[i];
        if(sz == Kn*Dn*Dn)          Wb = p;                       // 2097152
        else if(sz == Bn*Ln*Dn)     { if(nBig++==0) arg1=p; else arg2=p; }   // 131072
        else if(sz == 2*Dn*Kn)      { if(nMed++==0) Wd=p;   else Wg=p; }     // 16384
        else if(sz == Kn)           { if(nSmall==0) bg=p; else if(nSmall==1) bb=p; else u=p; nSmall++; }
    }
    float* out = (float*)d_out;

    static int attr_done = 0;
    if(!attr_done){
        cudaFuncSetAttribute(t_kernel,  cudaFuncAttributeMaxDynamicSharedMemorySize, Ln*Dn*4);
        cudaFuncSetAttribute(btp_kernel,cudaFuncAttributeMaxDynamicSharedMemorySize, 2*Ln*PAD*4);
        attr_done = 1;
    }

    proj_simple<<<64,256>>>(arg1, arg2, Wd, Wg);
    t_kernel  <<<Bn*Kn,256, Ln*Dn*4>>>(arg1, Wb);
    btp_kernel<<<Bn*Kn,256, 2*Ln*PAD*4>>>(arg2, bg, bb, u);
    reduce_kernel<<<128,256>>>(out);
}

// round 4
// speedup vs baseline: 1.6422x; 1.6422x over previous
#include <cuda_runtime.h>
#include <math.h>
#include <stdint.h>

#define Bn 8
#define Ln 64
#define Dn 256
#define Kn 32

// Scratch (device globals -- allocation is forbidden)
__device__ float g_A1d[Bn*Ln*Kn];
__device__ float g_A1g[Bn*Ln*Kn];
__device__ float g_A2d[Bn*Ln*Kn];
__device__ float g_A2g[Bn*Ln*Kn];
__device__ float g_T[(size_t)Bn*Kn*Ln*Dn];   // 16 MB: T[b,k,m,f]
__device__ float g_S[Bn*Kn*Ln*Ln];           // 4 MB: per-k scaled contributions

// ---- K0: projections. one thread per (b,r,k). idx = (b*64+r)*32 + k ----
__global__ void proj_simple(const float* __restrict__ arg1, const float* __restrict__ arg2,
                            const float* __restrict__ Wd, const float* __restrict__ Wg){
    int idx = blockIdx.x*blockDim.x + threadIdx.x;   // 0..16383
    int k = idx & 31;
    const float* a1 = arg1 + (idx>>5)*Dn;            // row (b*64+r)
    const float* a2 = arg2 + (idx>>5)*Dn;
    float s1d=0.f, s1g=0.f, s2d=0.f, s2g=0.f;
    for(int e=0;e<Dn;e++){
        float x1=a1[e], x2=a2[e];
        s1d = fmaf(x1, Wd[e*Kn+k],      s1d);
        s1g = fmaf(x1, Wg[e*Kn+k],      s1g);
        s2d = fmaf(x2, Wd[(Dn+e)*Kn+k], s2d);
        s2g = fmaf(x2, Wg[(Dn+e)*Kn+k], s2g);
    }
    g_A1d[idx]=s1d; g_A1g[idx]=s1g; g_A2d[idx]=s2d; g_A2g[idx]=s2g;
}

// ---- K1 v2: T[b,k,m,f] = sum_e arg1[b,m,e]*Wb[k,e,f]. block=(b,k) ----
// Register tile per thread: 4 m  x 16 f (as 4 x float4).
// tx = tid&15 -> f base pattern f = 64*j + 4*tx + c ; ty = tid>>4 -> m = 4*ty + i
#define T_SMEM_FLOATS (Ln*Dn + 32*Dn)     // a_sh 64x256 + W chunk 32x256 = 24576
__global__ void __launch_bounds__(256,2) t_kernel(const float* __restrict__ arg1,
                                                  const float* __restrict__ Wb){
    extern __shared__ float sh[];
    float* a_sh = sh;                     // [64][256]
    float* W_sh = sh + Ln*Dn;             // [32][256]
    int b = blockIdx.x >> 5, k = blockIdx.x & 31;
    int tid = threadIdx.x;
    int tx = tid & 15, ty = tid >> 4;

    const float* A1 = arg1 + b*Ln*Dn;
    // stage arg1[b] (linear copy, coalesced, conflict-free)
    #pragma unroll
    for(int r=0;r<16;r++){
        int i4 = tid + 256*r;             // float4 index 0..4095
        *(float4*)(a_sh + 4*i4) = *(const float4*)(A1 + 4*i4);
    }

    const float* Wk = Wb + (size_t)k*Dn*Dn;
    float4 acc[4][4];                     // [i(m)][j(f-group)]
    #pragma unroll
    for(int i=0;i<4;i++)
        #pragma unroll
        for(int j=0;j<4;j++) acc[i][j] = make_float4(0.f,0.f,0.f,0.f);

    for(int ec=0; ec<Dn; ec+=32){
        __syncthreads();                  // a_sh ready (1st) / prev W reads done
        // stage W chunk 32x256 (float4, coalesced, conflict-free)
        #pragma unroll
        for(int r=0;r<8;r++){
            int uI = tid + 256*r;         // 0..2047 float4s
            int e = uI >> 6, f4 = uI & 63;
            *(float4*)(W_sh + e*Dn + 4*f4) = *(const float4*)(Wk + (ec+e)*Dn + 4*f4);
        }
        __syncthreads();
        #pragma unroll 2
        for(int e=0;e<32;e++){
            float a[4];
            #pragma unroll
            for(int i=0;i<4;i++) a[i] = a_sh[(4*ty+i)*Dn + ec + e];
            float4 w[4];
            #pragma unroll
            for(int j=0;j<4;j++) w[j] = *(const float4*)(W_sh + e*Dn + 64*j + 4*tx);
            #pragma unroll
            for(int i=0;i<4;i++)
                #pragma unroll
                for(int j=0;j<4;j++){
                    acc[i][j].x = fmaf(a[i], w[j].x, acc[i][j].x);
                    acc[i][j].y = fmaf(a[i], w[j].y, acc[i][j].y);
                    acc[i][j].z = fmaf(a[i], w[j].z, acc[i][j].z);
                    acc[i][j].w = fmaf(a[i], w[j].w, acc[i][j].w);
                }
        }
    }
    float* Tb = g_T + (size_t)(b*Kn+k)*Ln*Dn;
    #pragma unroll
    for(int i=0;i<4;i++)
        #pragma unroll
        for(int j=0;j<4;j++)
            *(float4*)(Tb + (4*ty+i)*Dn + 64*j + 4*tx) = acc[i][j];
}

// ---- K2 v2: btp[b,k,m,n] = sum_f T[b,k,m,f]*arg2[b,n,f], + epilogue ----
// f chunked in halves of 128 so smem = 66KB -> occupancy 3, one wave.
#define PADB 129
#define BTP_SMEM_FLOATS (2*Ln*PADB)       // 16512
__global__ void __launch_bounds__(256,3) btp_kernel(const float* __restrict__ arg2,
        const float* __restrict__ bgp, const float* __restrict__ bp,
        const float* __restrict__ up){
    extern __shared__ float sh[];
    float* T_sh  = sh;                    // [64][129]
    float* A2_sh = sh + Ln*PADB;          // [64][129]
    int b = blockIdx.x >> 5, k = blockIdx.x & 31;
    int tid = threadIdx.x;
    const float* Tb = g_T + (size_t)(b*Kn+k)*Ln*Dn;
    const float* A2 = arg2 + b*Ln*Dn;

    int n = tid & 63, mg = tid >> 6;      // thread owns m = mg + 4*i
    float acc[16];
    #pragma unroll
    for(int i=0;i<16;i++) acc[i]=0.f;

    for(int c2=0;c2<2;c2++){
        __syncthreads();                  // prior chunk reads done
        for(int i=tid;i<Ln*128;i+=256){
            int r=i>>7, c=i&127;
            T_sh [r*PADB+c]=Tb[r*Dn + c2*128 + c];
            A2_sh[r*PADB+c]=A2[r*Dn + c2*128 + c];
        }
        __syncthreads();
        #pragma unroll 4
        for(int f=0;f<128;f++){
            float av = A2_sh[n*PADB+f];   // conflict-free ((n+f) mod 32 distinct)
            #pragma unroll
            for(int i=0;i<16;i++)
                acc[i] = fmaf(T_sh[(mg+4*i)*PADB+f], av, acc[i]);  // broadcast
        }
    }
    float bgk=bgp[k], bk=bp[k], uk=up[k];
    float a2d_v = g_A2d[(b*Ln+n)*Kn+k];
    float a2g_v = g_A2g[(b*Ln+n)*Kn+k];
    float* Sb = g_S + (size_t)(b*Kn+k)*Ln*Ln;
    #pragma unroll
    for(int i=0;i<16;i++){
        int m = mg + 4*i;
        float a1d_v = g_A1d[(b*Ln+m)*Kn+k];
        float a1g_v = g_A1g[(b*Ln+m)*Kn+k];
        float sln = tanhf(a1d_v + a2d_v);
        float xg  = a1g_v + a2g_v + bgk;
        float gt  = 1.0f/(1.0f+expf(-xg));
        Sb[m*Ln+n] = uk*(gt*acc[i] + (1.0f-gt)*sln + bk);
    }
}

// ---- K3: deterministic k-reduction ----
__global__ void reduce_kernel(float* __restrict__ out){
    int idx = blockIdx.x*blockDim.x + threadIdx.x;   // 32768
    int b = idx >> 12, mn = idx & 4095;
    const float* s = g_S + (size_t)b*Kn*4096 + mn;
    float acc = 0.f;
    #pragma unroll
    for(int kk=0; kk<Kn; kk++) acc += s[kk*4096];
    out[idx] = acc;
}

extern "C" void kernel_launch(void* const* d_in, const int* in_sizes, int n_in,
                              void* d_out, int out_size){
    // Defensive size-based input identification (robust to metadata ordering).
    const float *arg1=0,*arg2=0,*Wb=0,*Wd=0,*Wg=0,*bg=0,*bb=0,*u=0;
    int nBig=0, nMed=0, nSmall=0;
    for(int i=0;i<n_in;i++){
        int sz = in_sizes[i];
        const float* p = (const float*)d_in[i];
        if(sz == Kn*Dn*Dn)          Wb = p;                       // 2097152
        else if(sz == Bn*Ln*Dn)     { if(nBig++==0) arg1=p; else arg2=p; }   // 131072
        else if(sz == 2*Dn*Kn)      { if(nMed++==0) Wd=p;   else Wg=p; }     // 16384
        else if(sz == Kn)           { if(nSmall==0) bg=p; else if(nSmall==1) bb=p; else u=p; nSmall++; }
    }
    float* out = (float*)d_out;

    static int attr_done = 0;
    if(!attr_done){
        cudaFuncSetAttribute(t_kernel,  cudaFuncAttributeMaxDynamicSharedMemorySize, T_SMEM_FLOATS*4);
        cudaFuncSetAttribute(btp_kernel,cudaFuncAttributeMaxDynamicSharedMemorySize, BTP_SMEM_FLOATS*4);
        attr_done = 1;
    }

    proj_simple<<<64,256>>>(arg1, arg2, Wd, Wg);
    t_kernel  <<<Bn*Kn,256, T_SMEM_FLOATS*4>>>(arg1, Wb);
    btp_kernel<<<Bn*Kn,256, BTP_SMEM_FLOATS*4>>>(arg2, bg, bb, u);
    reduce_kernel<<<128,256>>>(out);
}

// round 5
// speedup vs baseline: 1.9771x; 1.2040x over previous
#include <cuda_runtime.h>
#include <math.h>
#include <stdint.h>

#define Bn 8
#define Ln 64
#define Dn 256
#define Kn 32

// Scratch (device globals -- allocation is forbidden)
__device__ float g_A1d[Bn*Ln*Kn];
__device__ float g_A1g[Bn*Ln*Kn];
__device__ float g_A2d[Bn*Ln*Kn];
__device__ float g_A2g[Bn*Ln*Kn];
__device__ float g_T[(size_t)Bn*Kn*Ln*Dn];   // 16 MB: T[b,k,m,f]
__device__ float g_S[Bn*Kn*Ln*Ln];           // 4 MB: per-k scaled contributions

// ---- packed f32x2 helpers (sm_103a) ----
__device__ __forceinline__ uint64_t pack2(float x, float y){
    uint64_t r; asm("mov.b64 %0, {%1,%2};" : "=l"(r) : "f"(x), "f"(y)); return r;
}
__device__ __forceinline__ uint64_t fma2(uint64_t a, uint64_t b, uint64_t c){
    uint64_t d; asm("fma.rn.f32x2 %0, %1, %2, %3;" : "=l"(d) : "l"(a), "l"(b), "l"(c)); return d;
}

// ---- K0: projections. one thread per (b,r,k). idx = (b*64+r)*32 + k ----
__global__ void proj_simple(const float* __restrict__ arg1, const float* __restrict__ arg2,
                            const float* __restrict__ Wd, const float* __restrict__ Wg){
    int idx = blockIdx.x*blockDim.x + threadIdx.x;   // 0..16383
    int k = idx & 31;
    const float* a1 = arg1 + (idx>>5)*Dn;            // row (b*64+r)
    const float* a2 = arg2 + (idx>>5)*Dn;
    float s1d=0.f, s1g=0.f, s2d=0.f, s2g=0.f;
    for(int e=0;e<Dn;e++){
        float x1=a1[e], x2=a2[e];
        s1d = fmaf(x1, Wd[e*Kn+k],      s1d);
        s1g = fmaf(x1, Wg[e*Kn+k],      s1g);
        s2d = fmaf(x2, Wd[(Dn+e)*Kn+k], s2d);
        s2g = fmaf(x2, Wg[(Dn+e)*Kn+k], s2g);
    }
    g_A1d[idx]=s1d; g_A1g[idx]=s1g; g_A2d[idx]=s2d; g_A2g[idx]=s2g;
}

// ---- K1 v3: T[b,k,m,f] = sum_e arg1[b,m,e]*Wb[k,e,f]. block=(b,k) ----
// Register tile per thread: 4 m x 16 f, accumulators as 8B-packed f32x2.
// tx = tid&15 -> f = 64*j + 4*tx + {0..3} ; ty = tid>>4 -> m = 4*ty + i
#define T_SMEM_FLOATS (Ln*Dn + 32*Dn)     // a_sh 64x256 + W chunk 32x256 = 24576
__global__ void __launch_bounds__(256,2) t_kernel(const float* __restrict__ arg1,
                                                  const float* __restrict__ Wb){
    extern __shared__ float sh[];
    float* a_sh = sh;                     // [64][256]
    float* W_sh = sh + Ln*Dn;             // [32][256]
    int b = blockIdx.x >> 5, k = blockIdx.x & 31;
    int tid = threadIdx.x;
    int tx = tid & 15, ty = tid >> 4;

    const float* A1 = arg1 + b*Ln*Dn;
    // stage arg1[b] (linear copy, coalesced, conflict-free)
    #pragma unroll
    for(int r=0;r<16;r++){
        int i4 = tid + 256*r;             // float4 index 0..4095
        *(float4*)(a_sh + 4*i4) = *(const float4*)(A1 + 4*i4);
    }

    const float* Wk = Wb + (size_t)k*Dn*Dn;
    uint64_t acc2[4][8];                  // [i(m)][f-pair within 16-f tile]
    #pragma unroll
    for(int i=0;i<4;i++)
        #pragma unroll
        for(int j=0;j<8;j++) acc2[i][j] = pack2(0.f, 0.f);

    for(int ec=0; ec<Dn; ec+=32){
        __syncthreads();                  // a_sh ready (1st) / prev W reads done
        // stage W chunk 32x256 (float4, coalesced, conflict-free)
        #pragma unroll
        for(int r=0;r<8;r++){
            int uI = tid + 256*r;         // 0..2047 float4s
            int e = uI >> 6, f4 = uI & 63;
            *(float4*)(W_sh + e*Dn + 4*f4) = *(const float4*)(Wk + (ec+e)*Dn + 4*f4);
        }
        __syncthreads();
        #pragma unroll 2
        for(int e=0;e<32;e++){
            uint64_t av[4];
            #pragma unroll
            for(int i=0;i<4;i++){
                float a = a_sh[(4*ty+i)*Dn + ec + e];
                av[i] = pack2(a, a);
            }
            #pragma unroll
            for(int j=0;j<4;j++){
                // 16 f per thread = 4 groups of float4 = 8 packed pairs
                uint64_t w0 = *(const uint64_t*)(W_sh + e*Dn + 64*j + 4*tx);
                uint64_t w1 = *(const uint64_t*)(W_sh + e*Dn + 64*j + 4*tx + 2);
                #pragma unroll
                for(int i=0;i<4;i++){
                    acc2[i][2*j]   = fma2(av[i], w0, acc2[i][2*j]);
                    acc2[i][2*j+1] = fma2(av[i], w1, acc2[i][2*j+1]);
                }
            }
        }
    }
    float* Tb = g_T + (size_t)(b*Kn+k)*Ln*Dn;
    #pragma unroll
    for(int i=0;i<4;i++)
        #pragma unroll
        for(int j=0;j<4;j++){
            *(uint64_t*)(Tb + (4*ty+i)*Dn + 64*j + 4*tx)     = acc2[i][2*j];
            *(uint64_t*)(Tb + (4*ty+i)*Dn + 64*j + 4*tx + 2) = acc2[i][2*j+1];
        }
}

// ---- K2 v3: btp[b,k,m,n] = sum_f T[b,k,m,f]*arg2[b,n,f], + epilogue ----
// 4m x 4n register tile: per f, 8 LDS + 16 FMA (FMA-bound).
// f chunked in halves of 128 so smem = 66KB -> occupancy 3, one wave.
#define PADB 129
#define BTP_SMEM_FLOATS (2*Ln*PADB)       // 16512
__global__ void __launch_bounds__(256,3) btp_kernel(const float* __restrict__ arg2,
        const float* __restrict__ bgp, const float* __restrict__ bp,
        const float* __restrict__ up){
    extern __shared__ float sh[];
    float* T_sh  = sh;                    // [64][129]
    float* A2_sh = sh + Ln*PADB;          // [64][129]
    int b = blockIdx.x >> 5, k = blockIdx.x & 31;
    int tid = threadIdx.x;
    const float* Tb = g_T + (size_t)(b*Kn+k)*Ln*Dn;
    const float* A2 = arg2 + b*Ln*Dn;

    int tx = tid & 15, ty = tid >> 4;     // m = 4*ty + i, n = 4*tx + jj
    float acc[4][4];
    #pragma unroll
    for(int i=0;i<4;i++)
        #pragma unroll
        for(int jj=0;jj<4;jj++) acc[i][jj]=0.f;

    for(int c2=0;c2<2;c2++){
        __syncthreads();                  // prior chunk reads done
        for(int i=tid;i<Ln*128;i+=256){
            int r=i>>7, c=i&127;
            T_sh [r*PADB+c]=Tb[r*Dn + c2*128 + c];
            A2_sh[r*PADB+c]=A2[r*Dn + c2*128 + c];
        }
        __syncthreads();
        #pragma unroll 4
        for(int f=0;f<128;f++){
            float tv[4], av[4];
            #pragma unroll
            for(int i=0;i<4;i++)  tv[i]  = T_sh [(4*ty+i)*PADB+f];   // broadcast
            #pragma unroll
            for(int jj=0;jj<4;jj++) av[jj] = A2_sh[(4*tx+jj)*PADB+f];
            #pragma unroll
            for(int i=0;i<4;i++)
                #pragma unroll
                for(int jj=0;jj<4;jj++)
                    acc[i][jj] = fmaf(tv[i], av[jj], acc[i][jj]);
        }
    }
    float bgk=bgp[k], bk=bp[k], uk=up[k];
    float a2d_v[4], a2g_v[4];
    #pragma unroll
    for(int jj=0;jj<4;jj++){
        int n = 4*tx + jj;
        a2d_v[jj] = g_A2d[(b*Ln+n)*Kn+k];
        a2g_v[jj] = g_A2g[(b*Ln+n)*Kn+k];
    }
    float* Sb = g_S + (size_t)(b*Kn+k)*Ln*Ln;
    #pragma unroll
    for(int i=0;i<4;i++){
        int m = 4*ty + i;
        float a1d_v = g_A1d[(b*Ln+m)*Kn+k];
        float a1g_v = g_A1g[(b*Ln+m)*Kn+k];
        float4 outv;
        float r[4];
        #pragma unroll
        for(int jj=0;jj<4;jj++){
            float sln = tanhf(a1d_v + a2d_v[jj]);
            float xg  = a1g_v + a2g_v[jj] + bgk;
            float gt  = 1.0f/(1.0f+expf(-xg));
            r[jj] = uk*(gt*acc[i][jj] + (1.0f-gt)*sln + bk);
        }
        outv.x=r[0]; outv.y=r[1]; outv.z=r[2]; outv.w=r[3];
        *(float4*)(Sb + m*Ln + 4*tx) = outv;
    }
}

// ---- K3: deterministic k-reduction ----
__global__ void reduce_kernel(float* __restrict__ out){
    int idx = blockIdx.x*blockDim.x + threadIdx.x;   // 32768
    int b = idx >> 12, mn = idx & 4095;
    const float* s = g_S + (size_t)b*Kn*4096 + mn;
    float acc = 0.f;
    #pragma unroll
    for(int kk=0; kk<Kn; kk++) acc += s[kk*4096];
    out[idx] = acc;
}

extern "C" void kernel_launch(void* const* d_in, const int* in_sizes, int n_in,
                              void* d_out, int out_size){
    // Defensive size-based input identification (robust to metadata ordering).
    const float *arg1=0,*arg2=0,*Wb=0,*Wd=0,*Wg=0,*bg=0,*bb=0,*u=0;
    int nBig=0, nMed=0, nSmall=0;
    for(int i=0;i<n_in;i++){
        int sz = in_sizes[i];
        const float* p = (const float*)d_in[i];
        if(sz == Kn*Dn*Dn)          Wb = p;                       // 2097152
        else if(sz == Bn*Ln*Dn)     { if(nBig++==0) arg1=p; else arg2=p; }   // 131072
        else if(sz == 2*Dn*Kn)      { if(nMed++==0) Wd=p;   else Wg=p; }     // 16384
        else if(sz == Kn)           { if(nSmall==0) bg=p; else if(nSmall==1) bb=p; else u=p; nSmall++; }
    }
    float* out = (float*)d_out;

    static int attr_done = 0;
    if(!attr_done){
        cudaFuncSetAttribute(t_kernel,  cudaFuncAttributeMaxDynamicSharedMemorySize, T_SMEM_FLOATS*4);
        cudaFuncSetAttribute(btp_kernel,cudaFuncAttributeMaxDynamicSharedMemorySize, BTP_SMEM_FLOATS*4);
        attr_done = 1;
    }

    proj_simple<<<64,256>>>(arg1, arg2, Wd, Wg);
    t_kernel  <<<Bn*Kn,256, T_SMEM_FLOATS*4>>>(arg1, Wb);
    btp_kernel<<<Bn*Kn,256, BTP_SMEM_FLOATS*4>>>(arg2, bg, bb, u);
    reduce_kernel<<<128,256>>>(out);
}

// round 6
// speedup vs baseline: 2.3874x; 1.2075x over previous
#include <cuda_runtime.h>
#include <math.h>
#include <stdint.h>

#define Bn 8
#define Ln 64
#define Dn 256
#define Kn 32

// Scratch (device globals -- allocation is forbidden)
__device__ float g_A1d[Bn*Ln*Kn];
__device__ float g_A1g[Bn*Ln*Kn];
__device__ float g_A2d[Bn*Ln*Kn];
__device__ float g_A2g[Bn*Ln*Kn];
__device__ float g_T[(size_t)Bn*Kn*Ln*Dn];   // 16 MB: T[b,k,m,f]
__device__ float g_S[Bn*Kn*Ln*Ln];           // 4 MB: per-k scaled contributions

// ---- packed f32x2 helpers (sm_103a) ----
__device__ __forceinline__ uint64_t pack2(float x, float y){
    uint64_t r; asm("mov.b64 %0, {%1,%2};" : "=l"(r) : "f"(x), "f"(y)); return r;
}
__device__ __forceinline__ uint64_t fma2(uint64_t a, uint64_t b, uint64_t c){
    uint64_t d; asm("fma.rn.f32x2 %0, %1, %2, %3;" : "=l"(d) : "l"(a), "l"(b), "l"(c)); return d;
}
__device__ __forceinline__ void unpack2(uint64_t v, float& x, float& y){
    asm("mov.b64 {%0,%1}, %2;" : "=f"(x), "=f"(y) : "l"(v));
}

// ---- K0 v2: projections. block = (b, 8-row group); 256 thr = 8 rows x 32 k ----
__global__ void __launch_bounds__(256) proj_kernel(
        const float* __restrict__ arg1, const float* __restrict__ arg2,
        const float* __restrict__ Wd, const float* __restrict__ Wg){
    __shared__ float a1_sh[8][Dn];
    __shared__ float a2_sh[8][Dn];
    __shared__ float w_sh[4][64][32];     // [arr][e-local][k], chunked over e
    int bx = blockIdx.x;                  // 0..63
    int b = bx >> 3, rg = bx & 7;
    int tid = threadIdx.x;
    int k = tid & 31, rloc = tid >> 5;    // row within group

    // stage 8 rows of arg1/arg2 (float4 coalesced)
    #pragma unroll
    for(int r4=0;r4<2;r4++){
        int i4 = tid + 256*r4;            // 0..511 float4s over 8x256
        int rr = i4 >> 6, c4 = i4 & 63;
        *(float4*)(&a1_sh[rr][4*c4]) = *(const float4*)(arg1 + (b*Ln + rg*8 + rr)*Dn + 4*c4);
        *(float4*)(&a2_sh[rr][4*c4]) = *(const float4*)(arg2 + (b*Ln + rg*8 + rr)*Dn + 4*c4);
    }

    float s1d=0.f, s1g=0.f, s2d=0.f, s2g=0.f;
    for(int ec=0; ec<Dn; ec+=64){
        __syncthreads();
        // stage 64-e chunks of Wd1, Wd2, Wg1, Wg2  (each 64x32 = 512 float4s)
        #pragma unroll
        for(int r4=0;r4<2;r4++){
            int i4 = tid + 256*r4;        // 0..511
            int e = i4 >> 3, j = i4 & 7;
            *(float4*)(&w_sh[0][e][4*j]) = *(const float4*)(Wd + (ec+e)*Kn + 4*j);
            *(float4*)(&w_sh[1][e][4*j]) = *(const float4*)(Wd + (Dn+ec+e)*Kn + 4*j);
            *(float4*)(&w_sh[2][e][4*j]) = *(const float4*)(Wg + (ec+e)*Kn + 4*j);
            *(float4*)(&w_sh[3][e][4*j]) = *(const float4*)(Wg + (Dn+ec+e)*Kn + 4*j);
        }
        __syncthreads();
        #pragma unroll 8
        for(int e=0;e<64;e++){
            float x1 = a1_sh[rloc][ec+e];         // broadcast
            float x2 = a2_sh[rloc][ec+e];
            s1d = fmaf(x1, w_sh[0][e][k], s1d);   // conflict-free
            s2d = fmaf(x2, w_sh[1][e][k], s2d);
            s1g = fmaf(x1, w_sh[2][e][k], s1g);
            s2g = fmaf(x2, w_sh[3][e][k], s2g);
        }
    }
    int idx = (b*Ln + rg*8 + rloc)*Kn + k;
    g_A1d[idx]=s1d; g_A1g[idx]=s1g; g_A2d[idx]=s2d; g_A2g[idx]=s2g;
}

// ---- K1 v3 (unchanged): T[b,k,m,f] = sum_e arg1[b,m,e]*Wb[k,e,f] ----
#define T_SMEM_FLOATS (Ln*Dn + 32*Dn)     // a_sh 64x256 + W chunk 32x256 = 24576
__global__ void __launch_bounds__(256,2) t_kernel(const float* __restrict__ arg1,
                                                  const float* __restrict__ Wb){
    extern __shared__ float sh[];
    float* a_sh = sh;                     // [64][256]
    float* W_sh = sh + Ln*Dn;             // [32][256]
    int b = blockIdx.x >> 5, k = blockIdx.x & 31;
    int tid = threadIdx.x;
    int tx = tid & 15, ty = tid >> 4;

    const float* A1 = arg1 + b*Ln*Dn;
    #pragma unroll
    for(int r=0;r<16;r++){
        int i4 = tid + 256*r;
        *(float4*)(a_sh + 4*i4) = *(const float4*)(A1 + 4*i4);
    }

    const float* Wk = Wb + (size_t)k*Dn*Dn;
    uint64_t acc2[4][8];
    #pragma unroll
    for(int i=0;i<4;i++)
        #pragma unroll
        for(int j=0;j<8;j++) acc2[i][j] = pack2(0.f, 0.f);

    for(int ec=0; ec<Dn; ec+=32){
        __syncthreads();
        #pragma unroll
        for(int r=0;r<8;r++){
            int uI = tid + 256*r;
            int e = uI >> 6, f4 = uI & 63;
            *(float4*)(W_sh + e*Dn + 4*f4) = *(const float4*)(Wk + (ec+e)*Dn + 4*f4);
        }
        __syncthreads();
        #pragma unroll 2
        for(int e=0;e<32;e++){
            uint64_t av[4];
            #pragma unroll
            for(int i=0;i<4;i++){
                float a = a_sh[(4*ty+i)*Dn + ec + e];
                av[i] = pack2(a, a);
            }
            #pragma unroll
            for(int j=0;j<4;j++){
                uint64_t w0 = *(const uint64_t*)(W_sh + e*Dn + 64*j + 4*tx);
                uint64_t w1 = *(const uint64_t*)(W_sh + e*Dn + 64*j + 4*tx + 2);
                #pragma unroll
                for(int i=0;i<4;i++){
                    acc2[i][2*j]   = fma2(av[i], w0, acc2[i][2*j]);
                    acc2[i][2*j+1] = fma2(av[i], w1, acc2[i][2*j+1]);
                }
            }
        }
    }
    float* Tb = g_T + (size_t)(b*Kn+k)*Ln*Dn;
    #pragma unroll
    for(int i=0;i<4;i++)
        #pragma unroll
        for(int j=0;j<4;j++){
            *(uint64_t*)(Tb + (4*ty+i)*Dn + 64*j + 4*tx)     = acc2[i][2*j];
            *(uint64_t*)(Tb + (4*ty+i)*Dn + 64*j + 4*tx + 2) = acc2[i][2*j+1];
        }
}

// ---- K2 v4: btp = T @ arg2^T with transposed A2 smem + packed f32x2 ----
#define PADB 129                          // T_sh row stride (odd -> conflict-free)
#define PADT 68                           // A2t row stride (16B-aligned float4 reads)
#define BTP_SMEM_FLOATS (Ln*PADB + 128*PADT)   // 8256 + 8704 = 16960 (67.8KB)
__global__ void __launch_bounds__(256,3) btp_kernel(const float* __restrict__ arg2,
        const float* __restrict__ bgp, const float* __restrict__ bp,
        const float* __restrict__ up){
    extern __shared__ float sh[];
    float* T_sh   = sh;                   // [64 m][129]  (f local)
    float* A2t_sh = sh + Ln*PADB;         // [128 f][68]  (n)
    int b = blockIdx.x >> 5, k = blockIdx.x & 31;
    int tid = threadIdx.x;
    const float* Tb = g_T + (size_t)(b*Kn+k)*Ln*Dn;
    const float* A2 = arg2 + b*Ln*Dn;

    int tx = tid & 15, ty = tid >> 4;     // m = 4*ty + i, n = 4*tx + jj
    uint64_t acc2[4][2];                  // packed over n pairs
    #pragma unroll
    for(int i=0;i<4;i++){ acc2[i][0]=pack2(0.f,0.f); acc2[i][1]=pack2(0.f,0.f); }

    for(int c2=0;c2<2;c2++){
        __syncthreads();                  // prior chunk reads done
        for(int i=tid;i<Ln*128;i+=256){
            int r=i>>7, c=i&127;          // r: m or n, c: f-local
            float tv = Tb[r*Dn + c2*128 + c];
            float av = A2[r*Dn + c2*128 + c];
            T_sh  [r*PADB + c] = tv;      // conflict-free
            A2t_sh[c*PADT + r] = av;      // transposed (4-way write conflict, staged once)
        }
        __syncthreads();
        #pragma unroll 4
        for(int f=0;f<128;f++){
            float4 av4 = *(const float4*)(A2t_sh + f*PADT + 4*tx);   // LDS.128
            uint64_t avp0 = pack2(av4.x, av4.y);
            uint64_t avp1 = pack2(av4.z, av4.w);
            #pragma unroll
            for(int i=0;i<4;i++){
                float t = T_sh[(4*ty+i)*PADB + f];                   // broadcast
                uint64_t tp = pack2(t, t);
                acc2[i][0] = fma2(tp, avp0, acc2[i][0]);
                acc2[i][1] = fma2(tp, avp1, acc2[i][1]);
            }
        }
    }
    float bgk=bgp[k], bk=bp[k], uk=up[k];
    float a2d_v[4], a2g_v[4];
    #pragma unroll
    for(int jj=0;jj<4;jj++){
        int n = 4*tx + jj;
        a2d_v[jj] = g_A2d[(b*Ln+n)*Kn+k];
        a2g_v[jj] = g_A2g[(b*Ln+n)*Kn+k];
    }
    float* Sb = g_S + (size_t)(b*Kn+k)*Ln*Ln;
    #pragma unroll
    for(int i=0;i<4;i++){
        int m = 4*ty + i;
        float a1d_v = g_A1d[(b*Ln+m)*Kn+k];
        float a1g_v = g_A1g[(b*Ln+m)*Kn+k];
        float acc[4];
        unpack2(acc2[i][0], acc[0], acc[1]);
        unpack2(acc2[i][1], acc[2], acc[3]);
        float r[4];
        #pragma unroll
        for(int jj=0;jj<4;jj++){
            float sln = tanhf(a1d_v + a2d_v[jj]);
            float xg  = a1g_v + a2g_v[jj] + bgk;
            float gt  = 1.0f/(1.0f+expf(-xg));
            r[jj] = uk*(gt*acc[jj] + (1.0f-gt)*sln + bk);
        }
        float4 outv; outv.x=r[0]; outv.y=r[1]; outv.z=r[2]; outv.w=r[3];
        *(float4*)(Sb + m*Ln + 4*tx) = outv;
    }
}

// ---- K3 v2: deterministic k-reduction, float4 ----
__global__ void reduce_kernel(float* __restrict__ out){
    int idx = blockIdx.x*blockDim.x + threadIdx.x;   // 0..8191 (float4 units)
    int b = idx >> 10;                               // 1024 float4 per b
    int mn4 = idx & 1023;
    const float* s = g_S + (size_t)b*Kn*4096 + 4*mn4;
    float4 acc = make_float4(0.f,0.f,0.f,0.f);
    #pragma unroll
    for(int kk=0; kk<Kn; kk++){
        float4 v = *(const float4*)(s + kk*4096);
        acc.x += v.x; acc.y += v.y; acc.z += v.z; acc.w += v.w;
    }
    *(float4*)(out + 4*idx) = acc;
}

extern "C" void kernel_launch(void* const* d_in, const int* in_sizes, int n_in,
                              void* d_out, int out_size){
    // Defensive size-based input identification (robust to metadata ordering).
    const float *arg1=0,*arg2=0,*Wb=0,*Wd=0,*Wg=0,*bg=0,*bb=0,*u=0;
    int nBig=0, nMed=0, nSmall=0;
    for(int i=0;i<n_in;i++){
        int sz = in_sizes[i];
        const float* p = (const float*)d_in[i];
        if(sz == Kn*Dn*Dn)          Wb = p;                       // 2097152
        else if(sz == Bn*Ln*Dn)     { if(nBig++==0) arg1=p; else arg2=p; }   // 131072
        else if(sz == 2*Dn*Kn)      { if(nMed++==0) Wd=p;   else Wg=p; }     // 16384
        else if(sz == Kn)           { if(nSmall==0) bg=p; else if(nSmall==1) bb=p; else u=p; nSmall++; }
    }
    float* out = (float*)d_out;

    static int attr_done = 0;
    if(!attr_done){
        cudaFuncSetAttribute(t_kernel,  cudaFuncAttributeMaxDynamicSharedMemorySize, T_SMEM_FLOATS*4);
        cudaFuncSetAttribute(btp_kernel,cudaFuncAttributeMaxDynamicSharedMemorySize, BTP_SMEM_FLOATS*4);
        attr_done = 1;
    }

    proj_kernel<<<64,256>>>(arg1, arg2, Wd, Wg);
    t_kernel  <<<Bn*Kn,256, T_SMEM_FLOATS*4>>>(arg1, Wb);
    btp_kernel<<<Bn*Kn,256, BTP_SMEM_FLOATS*4>>>(arg2, bg, bb, u);
    reduce_kernel<<<32,256>>>(out);
}

// round 8
// speedup vs baseline: 2.4644x; 1.0322x over previous
#include <cuda_runtime.h>
#include <math.h>
#include <stdint.h>

#define Bn 8
#define Ln 64
#define Dn 256
#define Kn 32

// Scratch (device globals -- allocation is forbidden)
__device__ float g_A1d[Bn*Ln*Kn];
__device__ float g_A1g[Bn*Ln*Kn];
__device__ float g_A2d[Bn*Ln*Kn];
__device__ float g_A2g[Bn*Ln*Kn];
__device__ float g_S[Bn*Kn*Ln*Ln];           // 4 MB: per-k scaled contributions

// ---- packed f32x2 helpers (sm_103a) ----
__device__ __forceinline__ uint64_t pack2(float x, float y){
    uint64_t r; asm("mov.b64 %0, {%1,%2};" : "=l"(r) : "f"(x), "f"(y)); return r;
}
__device__ __forceinline__ uint64_t fma2(uint64_t a, uint64_t b, uint64_t c){
    uint64_t d; asm("fma.rn.f32x2 %0, %1, %2, %3;" : "=l"(d) : "l"(a), "l"(b), "l"(c)); return d;
}
__device__ __forceinline__ void unpack2(uint64_t v, float& x, float& y){
    asm("mov.b64 {%0,%1}, %2;" : "=f"(x), "=f"(y) : "l"(v));
}

// ---- K0 v2: projections. block = (b, 8-row group); 256 thr = 8 rows x 32 k ----
__global__ void __launch_bounds__(256) proj_kernel(
        const float* __restrict__ arg1, const float* __restrict__ arg2,
        const float* __restrict__ Wd, const float* __restrict__ Wg){
    __shared__ float a1_sh[8][Dn];
    __shared__ float a2_sh[8][Dn];
    __shared__ float w_sh[4][64][32];     // [arr][e-local][k], chunked over e
    int bx = blockIdx.x;                  // 0..63
    int b = bx >> 3, rg = bx & 7;
    int tid = threadIdx.x;
    int k = tid & 31, rloc = tid >> 5;    // row within group

    #pragma unroll
    for(int r4=0;r4<2;r4++){
        int i4 = tid + 256*r4;            // 0..511 float4s over 8x256
        int rr = i4 >> 6, c4 = i4 & 63;
        *(float4*)(&a1_sh[rr][4*c4]) = *(const float4*)(arg1 + (b*Ln + rg*8 + rr)*Dn + 4*c4);
        *(float4*)(&a2_sh[rr][4*c4]) = *(const float4*)(arg2 + (b*Ln + rg*8 + rr)*Dn + 4*c4);
    }

    float s1d=0.f, s1g=0.f, s2d=0.f, s2g=0.f;
    for(int ec=0; ec<Dn; ec+=64){
        __syncthreads();
        #pragma unroll
        for(int r4=0;r4<2;r4++){
            int i4 = tid + 256*r4;        // 0..511
            int e = i4 >> 3, j = i4 & 7;
            *(float4*)(&w_sh[0][e][4*j]) = *(const float4*)(Wd + (ec+e)*Kn + 4*j);
            *(float4*)(&w_sh[1][e][4*j]) = *(const float4*)(Wd + (Dn+ec+e)*Kn + 4*j);
            *(float4*)(&w_sh[2][e][4*j]) = *(const float4*)(Wg + (ec+e)*Kn + 4*j);
            *(float4*)(&w_sh[3][e][4*j]) = *(const float4*)(Wg + (Dn+ec+e)*Kn + 4*j);
        }
        __syncthreads();
        #pragma unroll 8
        for(int e=0;e<64;e++){
            float x1 = a1_sh[rloc][ec+e];
            float x2 = a2_sh[rloc][ec+e];
            s1d = fmaf(x1, w_sh[0][e][k], s1d);
            s2d = fmaf(x2, w_sh[1][e][k], s2d);
            s1g = fmaf(x1, w_sh[2][e][k], s1g);
            s2g = fmaf(x2, w_sh[3][e][k], s2g);
        }
    }
    int idx = (b*Ln + rg*8 + rloc)*Kn + k;
    g_A1d[idx]=s1d; g_A1g[idx]=s1g; g_A2d[idx]=s2d; g_A2g[idx]=s2g;
}

// ================== K1 fused: T-GEMM (regs) + btp + epilogue ==================
// block = (b,k). Phase 1: T = arg1[b] @ Wb[k], T tile lives in acc2 registers
// (thread (tx,ty): m = 4*ty+i, f = 64*j + 4*tx + {0..3}).
// Phase 2 (per 128-f chunk): spill T chunk regs->smem (scalar stores -- PADB is
// odd so 8B stores would trap on odd rows), stage arg2 transposed, btp with
// packed f32x2, then gated epilogue -> g_S.
#define PADB 129                          // T_sh row stride (odd -> conflict-free reads)
#define PADT 68                           // A2t row stride (16B-aligned float4 reads)
#define FUSED_SMEM_FLOATS (Ln*Dn + 32*Dn) // phase1: a_sh 64x256 + W_sh 32x256 = 24576
                                          // phase2 overlay: 64*129 + 128*68 = 16960 (fits)
__global__ void __launch_bounds__(256,2) fused_kernel(
        const float* __restrict__ arg1, const float* __restrict__ arg2,
        const float* __restrict__ Wb,
        const float* __restrict__ bgp, const float* __restrict__ bp,
        const float* __restrict__ up){
    extern __shared__ float sh[];
    // phase-1 views
    float* a_sh = sh;                     // [64][256]
    float* W_sh = sh + Ln*Dn;             // [32][256]
    // phase-2 views (overlay)
    float* T_sh   = sh;                   // [64][129]
    float* A2t_sh = sh + Ln*PADB;         // [128][68]

    int b = blockIdx.x >> 5, k = blockIdx.x & 31;
    int tid = threadIdx.x;
    int tx = tid & 15, ty = tid >> 4;

    // ---------- phase 1 (verified t_kernel body) ----------
    const float* A1 = arg1 + b*Ln*Dn;
    #pragma unroll
    for(int r=0;r<16;r++){
        int i4 = tid + 256*r;
        *(float4*)(a_sh + 4*i4) = *(const float4*)(A1 + 4*i4);
    }

    const float* Wk = Wb + (size_t)k*Dn*Dn;
    uint64_t acc2[4][8];
    #pragma unroll
    for(int i=0;i<4;i++)
        #pragma unroll
        for(int j=0;j<8;j++) acc2[i][j] = pack2(0.f, 0.f);

    for(int ec=0; ec<Dn; ec+=32){
        __syncthreads();
        #pragma unroll
        for(int r=0;r<8;r++){
            int uI = tid + 256*r;
            int e = uI >> 6, f4 = uI & 63;
            *(float4*)(W_sh + e*Dn + 4*f4) = *(const float4*)(Wk + (ec+e)*Dn + 4*f4);
        }
        __syncthreads();
        #pragma unroll 2
        for(int e=0;e<32;e++){
            uint64_t av[4];
            #pragma unroll
            for(int i=0;i<4;i++){
                float a = a_sh[(4*ty+i)*Dn + ec + e];
                av[i] = pack2(a, a);
            }
            #pragma unroll
            for(int j=0;j<4;j++){
                uint64_t w0 = *(const uint64_t*)(W_sh + e*Dn + 64*j + 4*tx);
                uint64_t w1 = *(const uint64_t*)(W_sh + e*Dn + 64*j + 4*tx + 2);
                #pragma unroll
                for(int i=0;i<4;i++){
                    acc2[i][2*j]   = fma2(av[i], w0, acc2[i][2*j]);
                    acc2[i][2*j+1] = fma2(av[i], w1, acc2[i][2*j+1]);
                }
            }
        }
    }

    // ---------- phase 2 (verified btp body; T from registers) ----------
    const float* A2 = arg2 + b*Ln*Dn;
    uint64_t bacc[4][2];
    #pragma unroll
    for(int i=0;i<4;i++){ bacc[i][0]=pack2(0.f,0.f); bacc[i][1]=pack2(0.f,0.f); }

    for(int c2=0;c2<2;c2++){
        __syncthreads();                  // phase-1 smem reads / prior chunk reads done
        // spill T chunk: f_global = 64*(2*c2+j2) + 4*tx + c  -> f_local = 64*j2+4*tx+c
        // SCALAR stores: PADB odd => 8B stores would be misaligned for odd rows.
        #pragma unroll
        for(int j2=0;j2<2;j2++){
            int j = 2*c2 + j2;
            #pragma unroll
            for(int i=0;i<4;i++){
                int base = (4*ty+i)*PADB + 64*j2 + 4*tx;
                float v0,v1,v2,v3;
                unpack2(acc2[i][2*j],   v0, v1);
                unpack2(acc2[i][2*j+1], v2, v3);
                T_sh[base]   = v0;
                T_sh[base+1] = v1;
                T_sh[base+2] = v2;
                T_sh[base+3] = v3;
            }
        }
        // stage arg2 chunk transposed
        for(int i=tid;i<Ln*128;i+=256){
            int r=i>>7, c=i&127;          // r: n, c: f-local
            A2t_sh[c*PADT + r] = A2[r*Dn + c2*128 + c];
        }
        __syncthreads();
        #pragma unroll 4
        for(int f=0;f<128;f++){
            float4 av4 = *(const float4*)(A2t_sh + f*PADT + 4*tx);   // LDS.128
            uint64_t avp0 = pack2(av4.x, av4.y);
            uint64_t avp1 = pack2(av4.z, av4.w);
            #pragma unroll
            for(int i=0;i<4;i++){
                float t = T_sh[(4*ty+i)*PADB + f];                   // broadcast
                uint64_t tp = pack2(t, t);
                bacc[i][0] = fma2(tp, avp0, bacc[i][0]);
                bacc[i][1] = fma2(tp, avp1, bacc[i][1]);
            }
        }
    }

    // ---------- epilogue (verified) ----------
    float bgk=bgp[k], bk=bp[k], uk=up[k];
    float a2d_v[4], a2g_v[4];
    #pragma unroll
    for(int jj=0;jj<4;jj++){
        int n = 4*tx + jj;
        a2d_v[jj] = g_A2d[(b*Ln+n)*Kn+k];
        a2g_v[jj] = g_A2g[(b*Ln+n)*Kn+k];
    }
    float* Sb = g_S + (size_t)(b*Kn+k)*Ln*Ln;
    #pragma unroll
    for(int i=0;i<4;i++){
        int m = 4*ty + i;
        float a1d_v = g_A1d[(b*Ln+m)*Kn+k];
        float a1g_v = g_A1g[(b*Ln+m)*Kn+k];
        float acc[4];
        unpack2(bacc[i][0], acc[0], acc[1]);
        unpack2(bacc[i][1], acc[2], acc[3]);
        float r[4];
        #pragma unroll
        for(int jj=0;jj<4;jj++){
            float sln = tanhf(a1d_v + a2d_v[jj]);
            float xg  = a1g_v + a2g_v[jj] + bgk;
            float gt  = 1.0f/(1.0f+expf(-xg));
            r[jj] = uk*(gt*acc[jj] + (1.0f-gt)*sln + bk);
        }
        float4 outv; outv.x=r[0]; outv.y=r[1]; outv.z=r[2]; outv.w=r[3];
        *(float4*)(Sb + m*Ln + 4*tx) = outv;
    }
}

// ---- K3: deterministic k-reduction (scalar, grid 128 — measured fastest) ----
__global__ void reduce_kernel(float* __restrict__ out){
    int idx = blockIdx.x*blockDim.x + threadIdx.x;   // 32768
    int b = idx >> 12, mn = idx & 4095;
    const float* s = g_S + (size_t)b*Kn*4096 + mn;
    float acc = 0.f;
    #pragma unroll
    for(int kk=0; kk<Kn; kk++) acc += s[kk*4096];
    out[idx] = acc;
}

extern "C" void kernel_launch(void* const* d_in, const int* in_sizes, int n_in,
                              void* d_out, int out_size){
    // Defensive size-based input identification (robust to metadata ordering).
    const float *arg1=0,*arg2=0,*Wb=0,*Wd=0,*Wg=0,*bg=0,*bb=0,*u=0;
    int nBig=0, nMed=0, nSmall=0;
    for(int i=0;i<n_in;i++){
        int sz = in_sizes[i];
        const float* p = (const float*)d_in[i];
        if(sz == Kn*Dn*Dn)          Wb = p;                       // 2097152
        else if(sz == Bn*Ln*Dn)     { if(nBig++==0) arg1=p; else arg2=p; }   // 131072
        else if(sz == 2*Dn*Kn)      { if(nMed++==0) Wd=p;   else Wg=p; }     // 16384
        else if(sz == Kn)           { if(nSmall==0) bg=p; else if(nSmall==1) bb=p; else u=p; nSmall++; }
    }
    float* out = (float*)d_out;

    static int attr_done = 0;
    if(!attr_done){
        cudaFuncSetAttribute(fused_kernel, cudaFuncAttributeMaxDynamicSharedMemorySize, FUSED_SMEM_FLOATS*4);
        attr_done = 1;
    }

    proj_kernel <<<64,256>>>(arg1, arg2, Wd, Wg);
    fused_kernel<<<Bn*Kn,256, FUSED_SMEM_FLOATS*4>>>(arg1, arg2, Wb, bg, bb, u);
    reduce_kernel<<<128,256>>>(out);
}

// round 9
// speedup vs baseline: 2.6496x; 1.0752x over previous
#include <cuda_runtime.h>
#include <math.h>
#include <stdint.h>

#define Bn 8
#define Ln 64
#define Dn 256
#define Kn 32

// Scratch (device globals -- allocation is forbidden)
__device__ float g_S[Bn*Kn*Ln*Ln];           // 4 MB: per-k scaled contributions

// ---- packed f32x2 helpers (sm_103a) ----
__device__ __forceinline__ uint64_t pack2(float x, float y){
    uint64_t r; asm("mov.b64 %0, {%1,%2};" : "=l"(r) : "f"(x), "f"(y)); return r;
}
__device__ __forceinline__ uint64_t fma2(uint64_t a, uint64_t b, uint64_t c){
    uint64_t d; asm("fma.rn.f32x2 %0, %1, %2, %3;" : "=l"(d) : "l"(a), "l"(b), "l"(c)); return d;
}
__device__ __forceinline__ void unpack2(uint64_t v, float& x, float& y){
    asm("mov.b64 {%0,%1}, %2;" : "=f"(x), "=f"(y) : "l"(v));
}

// ================== fully fused kernel: proj + T-GEMM + btp + epilogue =======
// block = (b,k).
// smem layout (floats):
//   phase-1 view: a_sh [64][257] @0 (16448) ; W_sh [32][256] @16448 (8192)
//   phase-2 view: T_sh [64][129] @0 (8256)  ; A2t_sh [128][68] @8256 (8704)
//   persistent:   Wcol [4][256] @24640 (1024) ; P_sh [256] @25664
#define A_STR 257
#define PADB 129
#define PADT 68
#define OFF_W    (Ln*A_STR)               // 16448
#define OFF_WCOL (OFF_W + 32*Dn)          // 24640
#define OFF_P    (OFF_WCOL + 4*Dn)        // 25664
#define FUSED_SMEM_FLOATS (OFF_P + 4*Ln)  // 25920 -> 103680 B
__global__ void __launch_bounds__(256,2) fused_kernel(
        const float* __restrict__ arg1, const float* __restrict__ arg2,
        const float* __restrict__ Wb,
        const float* __restrict__ Wd, const float* __restrict__ Wg,
        const float* __restrict__ bgp, const float* __restrict__ bp,
        const float* __restrict__ up){
    extern __shared__ float sh[];
    float* a_sh   = sh;                   // [64][257]
    float* W_sh   = sh + OFF_W;           // [32][256]
    float* T_sh   = sh;                   // [64][129]  (phase-2 overlay)
    float* A2t_sh = sh + Ln*PADB;         // [128][68]  (phase-2 overlay)
    float* Wcol   = sh + OFF_WCOL;        // [4][256]: Wd1k, Wg1k, Wd2k, Wg2k
    float* P_sh   = sh + OFF_P;           // a1d[64] a1g[64] a2d[64] a2g[64]

    int b = blockIdx.x >> 5, k = blockIdx.x & 31;
    int tid = threadIdx.x;
    int txf = tid & 31, tym = tid >> 5;   // phase-1 map: f-lane, m-group(=warp)

    // ---- stage Wd/Wg columns for this k (tiny) ----
    {
        int arr = tid >> 6, e = tid & 63;
        #pragma unroll
        for(int r=0;r<4;r++){
            int ee = 64*r + e;
            float v;
            if(arr==0)      v = Wd[ee*Kn + k];
            else if(arr==1) v = Wg[ee*Kn + k];
            else if(arr==2) v = Wd[(Dn+ee)*Kn + k];
            else            v = Wg[(Dn+ee)*Kn + k];
            Wcol[arr*Dn + ee] = v;
        }
    }

    // ---- stage arg1[b] into a_sh (stride 257; float4 LDG + scalar STS) ----
    const float* A1 = arg1 + b*Ln*Dn;
    #pragma unroll
    for(int r=0;r<16;r++){
        int i4 = tid + 256*r;             // 0..4095
        int m = i4 >> 6, c4 = i4 & 63;
        float4 v = *(const float4*)(A1 + m*Dn + 4*c4);
        float* dst = a_sh + m*A_STR + 4*c4;
        dst[0]=v.x; dst[1]=v.y; dst[2]=v.z; dst[3]=v.w;
    }

    // ---------- phase 1: T = arg1[b] @ Wb[k], 8m x 8f per thread ----------
    // thread (txf,tym): m = 8*tym + i (i<8), f = 128*jj + 4*txf + c (jj<2,c<4)
    const float* Wk = Wb + (size_t)k*Dn*Dn;
    uint64_t acc2[8][4];                  // [i][2*jj + pair]
    #pragma unroll
    for(int i=0;i<8;i++)
        #pragma unroll
        for(int j=0;j<4;j++) acc2[i][j] = pack2(0.f, 0.f);

    for(int ec=0; ec<Dn; ec+=32){
        __syncthreads();
        #pragma unroll
        for(int r=0;r<8;r++){
            int uI = tid + 256*r;
            int e = uI >> 6, f4 = uI & 63;
            *(float4*)(W_sh + e*Dn + 4*f4) = *(const float4*)(Wk + (ec+e)*Dn + 4*f4);
        }
        __syncthreads();
        #pragma unroll 2
        for(int e=0;e<32;e++){
            uint64_t av[8];
            #pragma unroll
            for(int i=0;i<8;i++){
                float a = a_sh[(8*tym+i)*A_STR + ec + e];   // warp-uniform bcast
                av[i] = pack2(a, a);
            }
            #pragma unroll
            for(int jj=0;jj<2;jj++){
                uint64_t w0 = *(const uint64_t*)(W_sh + e*Dn + 128*jj + 4*txf);
                uint64_t w1 = *(const uint64_t*)(W_sh + e*Dn + 128*jj + 4*txf + 2);
                #pragma unroll
                for(int i=0;i<8;i++){
                    acc2[i][2*jj]   = fma2(av[i], w0, acc2[i][2*jj]);
                    acc2[i][2*jj+1] = fma2(av[i], w1, acc2[i][2*jj+1]);
                }
            }
        }
    }

    // ---- a1d/a1g from a_sh (before phase-2 overlay destroys it) ----
    __syncthreads();                      // all phase-1 reads of a_sh/W_sh done
    if(tid < 128){
        int m = tid & 63, arr = tid >> 6; // 0=d, 1=g (warp-uniform arr)
        float s = 0.f;
        #pragma unroll 8
        for(int e=0;e<Dn;e++)
            s = fmaf(a_sh[m*A_STR + e], Wcol[arr*Dn + e], s);
        P_sh[arr*64 + m] = s;
    }

    // ---------- phase 2: btp = T @ arg2[b]^T + a2 projections ----------
    const float* A2 = arg2 + b*Ln*Dn;
    int tx = tid & 15, ty = tid >> 4;     // phase-2 map: m = 4*ty+i, n = 4*tx+jj
    uint64_t bacc[4][2];
    #pragma unroll
    for(int i=0;i<4;i++){ bacc[i][0]=pack2(0.f,0.f); bacc[i][1]=pack2(0.f,0.f); }
    float s2 = 0.f;                       // a2 projection accumulator (tid<128)

    for(int c2=0;c2<2;c2++){
        __syncthreads();                  // a1-dot reads / prior chunk reads done
        // spill T chunk from regs: f_local = 4*txf + c  (group jj = c2)
        #pragma unroll
        for(int i=0;i<8;i++){
            int base = (8*tym+i)*PADB + 4*txf;
            float v0,v1,v2,v3;
            unpack2(acc2[i][2*c2],   v0, v1);
            unpack2(acc2[i][2*c2+1], v2, v3);
            T_sh[base]   = v0;
            T_sh[base+1] = v1;
            T_sh[base+2] = v2;
            T_sh[base+3] = v3;
        }
        // stage arg2 chunk transposed
        for(int i=tid;i<Ln*128;i+=256){
            int r=i>>7, c=i&127;          // r: n, c: f-local
            A2t_sh[c*PADT + r] = A2[r*Dn + c2*128 + c];
        }
        __syncthreads();
        #pragma unroll 4
        for(int f=0;f<128;f++){
            float4 av4 = *(const float4*)(A2t_sh + f*PADT + 4*tx);   // LDS.128
            uint64_t avp0 = pack2(av4.x, av4.y);
            uint64_t avp1 = pack2(av4.z, av4.w);
            #pragma unroll
            for(int i=0;i<4;i++){
                float t = T_sh[(4*ty+i)*PADB + f];                   // broadcast
                uint64_t tp = pack2(t, t);
                bacc[i][0] = fma2(tp, avp0, bacc[i][0]);
                bacc[i][1] = fma2(tp, avp1, bacc[i][1]);
            }
        }
        // a2d/a2g partial dots from this staged chunk
        if(tid < 128){
            int n = tid & 63, arr = tid >> 6;
            #pragma unroll 8
            for(int f=0;f<128;f++)
                s2 = fmaf(A2t_sh[f*PADT + n], Wcol[(2+arr)*Dn + c2*128 + f], s2);
        }
    }
    if(tid < 128){
        int n = tid & 63, arr = tid >> 6;
        P_sh[128 + arr*64 + n] = s2;
    }
    __syncthreads();                      // P_sh complete

    // ---------- epilogue ----------
    float bgk=bgp[k], bk=bp[k], uk=up[k];
    float a2d_v[4], a2g_v[4];
    #pragma unroll
    for(int jj=0;jj<4;jj++){
        int n = 4*tx + jj;
        a2d_v[jj] = P_sh[128 + n];
        a2g_v[jj] = P_sh[192 + n];
    }
    float* Sb = g_S + (size_t)(b*Kn + k)*Ln*Ln;
    #pragma unroll
    for(int i=0;i<4;i++){
        int m = 4*ty + i;
        float a1d_v = P_sh[m];
        float a1g_v = P_sh[64 + m];
        float acc[4];
        unpack2(bacc[i][0], acc[0], acc[1]);
        unpack2(bacc[i][1], acc[2], acc[3]);
        float r[4];
        #pragma unroll
        for(int jj=0;jj<4;jj++){
            float sln = tanhf(a1d_v + a2d_v[jj]);
            float xg  = a1g_v + a2g_v[jj] + bgk;
            float gt  = 1.0f/(1.0f+expf(-xg));
            r[jj] = uk*(gt*acc[jj] + (1.0f-gt)*sln + bk);
        }
        float4 outv; outv.x=r[0]; outv.y=r[1]; outv.z=r[2]; outv.w=r[3];
        *(float4*)(Sb + m*Ln + 4*tx) = outv;
    }
}

// ---- K3: deterministic k-reduction (scalar, grid 128 — measured fastest) ----
__global__ void reduce_kernel(float* __restrict__ out){
    int idx = blockIdx.x*blockDim.x + threadIdx.x;   // 32768
    int b = idx >> 12, mn = idx & 4095;
    const float* s = g_S + (size_t)b*Kn*4096 + mn;
    float acc = 0.f;
    #pragma unroll
    for(int kk=0; kk<Kn; kk++) acc += s[kk*4096];
    out[idx] = acc;
}

extern "C" void kernel_launch(void* const* d_in, const int* in_sizes, int n_in,
                              void* d_out, int out_size){
    // Defensive size-based input identification (robust to metadata ordering).
    const float *arg1=0,*arg2=0,*Wb=0,*Wd=0,*Wg=0,*bg=0,*bb=0,*u=0;
    int nBig=0, nMed=0, nSmall=0;
    for(int i=0;i<n_in;i++){
        int sz = in_sizes[i];
        const float* p = (const float*)d_in[i];
        if(sz == Kn*Dn*Dn)          Wb = p;                       // 2097152
        else if(sz == Bn*Ln*Dn)     { if(nBig++==0) arg1=p; else arg2=p; }   // 131072
        else if(sz == 2*Dn*Kn)      { if(nMed++==0) Wd=p;   else Wg=p; }     // 16384
        else if(sz == Kn)           { if(nSmall==0) bg=p; else if(nSmall==1) bb=p; else u=p; nSmall++; }
    }
    float* out = (float*)d_out;

    static int attr_done = 0;
    if(!attr_done){
        cudaFuncSetAttribute(fused_kernel, cudaFuncAttributeMaxDynamicSharedMemorySize, FUSED_SMEM_FLOATS*4);
        attr_done = 1;
    }

    fused_kernel<<<Bn*Kn,256, FUSED_SMEM_FLOATS*4>>>(arg1, arg2, Wb, Wd, Wg, bg, bb, u);
    reduce_kernel<<<128,256>>>(out);
}

// round 10
// speedup vs baseline: 2.8205x; 1.0645x over previous
#include <cuda_runtime.h>
#include <math.h>
#include <stdint.h>

#define Bn 8
#define Ln 64
#define Dn 256
#define Kn 32

// Scratch (device globals -- allocation is forbidden)
__device__ float g_S[Bn*Kn*Ln*Ln];           // 4 MB: per-k scaled contributions

// ---- packed f32x2 helpers (sm_103a) ----
__device__ __forceinline__ uint64_t pack2(float x, float y){
    uint64_t r; asm("mov.b64 %0, {%1,%2};" : "=l"(r) : "f"(x), "f"(y)); return r;
}
__device__ __forceinline__ uint64_t fma2(uint64_t a, uint64_t b, uint64_t c){
    uint64_t d; asm("fma.rn.f32x2 %0, %1, %2, %3;" : "=l"(d) : "l"(a), "l"(b), "l"(c)); return d;
}
__device__ __forceinline__ void unpack2(uint64_t v, float& x, float& y){
    asm("mov.b64 {%0,%1}, %2;" : "=f"(x), "=f"(y) : "l"(v));
}
// ---- cp.async helpers ----
__device__ __forceinline__ void cp16(uint32_t dst, const float* src){
    asm volatile("cp.async.cg.shared.global [%0], [%1], 16;" :: "r"(dst), "l"(src));
}
#define CP_COMMIT() asm volatile("cp.async.commit_group;")
#define CP_WAIT0()  asm volatile("cp.async.wait_group 0;")

// ================== fully fused kernel: proj + T-GEMM + btp + epilogue =======
// block = (b,k).
// smem layout (floats):
//   phase-1 view: a_sh [64][257] @0 (16448) ; W ping-pong 2x[16][256] @16448 (8192)
//   phase-2 view: T_sh [64][129] @0 (8256)  ; A2t_sh [128][68] @8256 (8704)
//   persistent:   Wcol [4][256] @24640 (1024) ; P2 [512] @25664
#define A_STR 257
#define PADB 129
#define PADT 68
#define OFF_W    (Ln*A_STR)               // 16448 (byte offset 65792, 16B aligned)
#define OFF_WCOL (OFF_W + 32*Dn)          // 24640
#define OFF_P2   (OFF_WCOL + 4*Dn)        // 25664
#define FUSED_SMEM_FLOATS (OFF_P2 + 512)  // 26176 -> 104704 B
__global__ void __launch_bounds__(256,2) fused_kernel(
        const float* __restrict__ arg1, const float* __restrict__ arg2,
        const float* __restrict__ Wb,
        const float* __restrict__ Wd, const float* __restrict__ Wg,
        const float* __restrict__ bgp, const float* __restrict__ bp,
        const float* __restrict__ up){
    extern __shared__ float sh[];
    float* a_sh   = sh;                   // [64][257]
    float* W_sh   = sh + OFF_W;           // 2 x [16][256] ping-pong
    float* T_sh   = sh;                   // [64][129]  (phase-2 overlay)
    float* A2t_sh = sh + Ln*PADB;         // [128][68]  (phase-2 overlay)
    float* Wcol   = sh + OFF_WCOL;        // [4][256]: Wd1k, Wg1k, Wd2k, Wg2k
    float* P2     = sh + OFF_P2;          // split projection partials (512)

    int b = blockIdx.x >> 5, k = blockIdx.x & 31;
    int tid = threadIdx.x;
    int txf = tid & 31, tym = tid >> 5;   // phase-1 map: f-lane, m-group(=warp)
    uint32_t W_smem = (uint32_t)__cvta_generic_to_shared(W_sh);

    // ---- stage Wd/Wg columns for this k (tiny) ----
    {
        int arr = tid >> 6, e = tid & 63;
        #pragma unroll
        for(int r=0;r<4;r++){
            int ee = 64*r + e;
            float v;
            if(arr==0)      v = Wd[ee*Kn + k];
            else if(arr==1) v = Wg[ee*Kn + k];
            else if(arr==2) v = Wd[(Dn+ee)*Kn + k];
            else            v = Wg[(Dn+ee)*Kn + k];
            Wcol[arr*Dn + ee] = v;
        }
    }

    const float* Wk = Wb + (size_t)k*Dn*Dn;
    // ---- prefetch W chunk 0 (16e x 256f) into buffer 0 ----
    #pragma unroll
    for(int r=0;r<4;r++){
        int uI = tid + 256*r;             // 0..1023 float4s
        int e = uI >> 6, f4 = uI & 63;
        cp16(W_smem + (e*Dn + 4*f4)*4, Wk + e*Dn + 4*f4);
    }
    CP_COMMIT();

    // ---- stage arg1[b] into a_sh (stride 257; float4 LDG + scalar STS) ----
    const float* A1 = arg1 + b*Ln*Dn;
    #pragma unroll
    for(int r=0;r<16;r++){
        int i4 = tid + 256*r;             // 0..4095
        int m = i4 >> 6, c4 = i4 & 63;
        float4 v = *(const float4*)(A1 + m*Dn + 4*c4);
        float* dst = a_sh + m*A_STR + 4*c4;
        dst[0]=v.x; dst[1]=v.y; dst[2]=v.z; dst[3]=v.w;
    }

    // ---------- phase 1: T = arg1[b] @ Wb[k], 8m x 8f per thread ----------
    // thread (txf,tym): m = 8*tym + i (i<8), f = 128*jj + 4*txf + c (jj<2,c<4)
    uint64_t acc2[8][4];                  // [i][2*jj + pair]
    #pragma unroll
    for(int i=0;i<8;i++)
        #pragma unroll
        for(int j=0;j<4;j++) acc2[i][j] = pack2(0.f, 0.f);

    CP_WAIT0();
    __syncthreads();                      // a_sh + W chunk 0 ready

    for(int c=0; c<16; c++){
        float* Wcur = W_sh + (c&1)*(16*Dn);
        if(c < 15){
            // async prefetch next chunk into the other buffer
            uint32_t dstb = W_smem + ((c+1)&1)*(16*Dn)*4;
            const float* srcb = Wk + (c+1)*16*Dn;
            #pragma unroll
            for(int r=0;r<4;r++){
                int uI = tid + 256*r;
                int e = uI >> 6, f4 = uI & 63;
                cp16(dstb + (e*Dn + 4*f4)*4, srcb + e*Dn + 4*f4);
            }
            CP_COMMIT();
        }
        int ec = c*16;
        #pragma unroll 2
        for(int e=0;e<16;e++){
            uint64_t av[8];
            #pragma unroll
            for(int i=0;i<8;i++){
                float a = a_sh[(8*tym+i)*A_STR + ec + e];   // warp-uniform bcast
                av[i] = pack2(a, a);
            }
            #pragma unroll
            for(int jj=0;jj<2;jj++){
                uint64_t w0 = *(const uint64_t*)(Wcur + e*Dn + 128*jj + 4*txf);
                uint64_t w1 = *(const uint64_t*)(Wcur + e*Dn + 128*jj + 4*txf + 2);
                #pragma unroll
                for(int i=0;i<8;i++){
                    acc2[i][2*jj]   = fma2(av[i], w0, acc2[i][2*jj]);
                    acc2[i][2*jj+1] = fma2(av[i], w1, acc2[i][2*jj+1]);
                }
            }
        }
        if(c < 15) CP_WAIT0();
        __syncthreads();                  // next buffer visible; cur buffer free
    }

    // ---- a1d/a1g from a_sh, split across ALL 256 threads (half-e each) ----
    {
        int m = tid & 63, arr = (tid >> 6) & 1, half = tid >> 7;
        int e0 = half*128;
        float s = 0.f;
        #pragma unroll 8
        for(int e=e0;e<e0+128;e++)
            s = fmaf(a_sh[m*A_STR + e], Wcol[arr*Dn + e], s);
        P2[half*128 + arr*64 + m] = s;
    }

    // ---------- phase 2: btp = T @ arg2[b]^T + a2 projections ----------
    const float* A2 = arg2 + b*Ln*Dn;
    int tx = tid & 15, ty = tid >> 4;     // phase-2 map: m = 4*ty+i, n = 4*tx+jj
    uint64_t bacc[4][2];
    #pragma unroll
    for(int i=0;i<4;i++){ bacc[i][0]=pack2(0.f,0.f); bacc[i][1]=pack2(0.f,0.f); }
    float s2 = 0.f;                       // a2 projection accumulator

    for(int c2=0;c2<2;c2++){
        __syncthreads();                  // a1-dot reads / prior chunk reads done
        // spill T chunk from regs: f_local = 4*txf + c  (group jj = c2)
        #pragma unroll
        for(int i=0;i<8;i++){
            int base = (8*tym+i)*PADB + 4*txf;
            float v0,v1,v2,v3;
            unpack2(acc2[i][2*c2],   v0, v1);
            unpack2(acc2[i][2*c2+1], v2, v3);
            T_sh[base]   = v0;
            T_sh[base+1] = v1;
            T_sh[base+2] = v2;
            T_sh[base+3] = v3;
        }
        // stage arg2 chunk transposed
        for(int i=tid;i<Ln*128;i+=256){
            int r=i>>7, c=i&127;          // r: n, c: f-local
            A2t_sh[c*PADT + r] = A2[r*Dn + c2*128 + c];
        }
        __syncthreads();
        #pragma unroll 4
        for(int f=0;f<128;f++){
            float4 av4 = *(const float4*)(A2t_sh + f*PADT + 4*tx);   // LDS.128
            uint64_t avp0 = pack2(av4.x, av4.y);
            uint64_t avp1 = pack2(av4.z, av4.w);
            #pragma unroll
            for(int i=0;i<4;i++){
                float t = T_sh[(4*ty+i)*PADB + f];                   // broadcast
                uint64_t tp = pack2(t, t);
                bacc[i][0] = fma2(tp, avp0, bacc[i][0]);
                bacc[i][1] = fma2(tp, avp1, bacc[i][1]);
            }
        }
        // a2d/a2g partial dots from this staged chunk (all 256 threads, half-f)
        {
            int n = tid & 63, arr = (tid >> 6) & 1, half = tid >> 7;
            int f0 = half*64;
            #pragma unroll 8
            for(int f=f0;f<f0+64;f++)
                s2 = fmaf(A2t_sh[f*PADT + n], Wcol[(2+arr)*Dn + c2*128 + f], s2);
        }
    }
    {
        int n = tid & 63, arr = (tid >> 6) & 1, half = tid >> 7;
        P2[256 + half*128 + arr*64 + n] = s2;
    }
    __syncthreads();                      // P2 complete

    // ---------- epilogue ----------
    float bgk=bgp[k], bk=bp[k], uk=up[k];
    float a2d_v[4], a2g_v[4];
    #pragma unroll
    for(int jj=0;jj<4;jj++){
        int n = 4*tx + jj;
        a2d_v[jj] = P2[256 + n]      + P2[384 + n];
        a2g_v[jj] = P2[256 + 64 + n] + P2[448 + n];
    }
    float* Sb = g_S + (size_t)(b*Kn + k)*Ln*Ln;
    #pragma unroll
    for(int i=0;i<4;i++){
        int m = 4*ty + i;
        float a1d_v = P2[m]      + P2[128 + m];
        float a1g_v = P2[64 + m] + P2[192 + m];
        float acc[4];
        unpack2(bacc[i][0], acc[0], acc[1]);
        unpack2(bacc[i][1], acc[2], acc[3]);
        float r[4];
        #pragma unroll
        for(int jj=0;jj<4;jj++){
            float sln = tanhf(a1d_v + a2d_v[jj]);
            float xg  = a1g_v + a2g_v[jj] + bgk;
            float gt  = 1.0f/(1.0f+expf(-xg));
            r[jj] = uk*(gt*acc[jj] + (1.0f-gt)*sln + bk);
        }
        float4 outv; outv.x=r[0]; outv.y=r[1]; outv.z=r[2]; outv.w=r[3];
        *(float4*)(Sb + m*Ln + 4*tx) = outv;
    }
}

// ---- K3: deterministic k-reduction (scalar, grid 128 — measured fastest) ----
__global__ void reduce_kernel(float* __restrict__ out){
    int idx = blockIdx.x*blockDim.x + threadIdx.x;   // 32768
    int b = idx >> 12, mn = idx & 4095;
    const float* s = g_S + (size_t)b*Kn*4096 + mn;
    float acc = 0.f;
    #pragma unroll
    for(int kk=0; kk<Kn; kk++) acc += s[kk*4096];
    out[idx] = acc;
}

extern "C" void kernel_launch(void* const* d_in, const int* in_sizes, int n_in,
                              void* d_out, int out_size){
    // Defensive size-based input identification (robust to metadata ordering).
    const float *arg1=0,*arg2=0,*Wb=0,*Wd=0,*Wg=0,*bg=0,*bb=0,*u=0;
    int nBig=0, nMed=0, nSmall=0;
    for(int i=0;i<n_in;i++){
        int sz = in_sizes[i];
        const float* p = (const float*)d_in[i];
        if(sz == Kn*Dn*Dn)          Wb = p;                       // 2097152
        else if(sz == Bn*Ln*Dn)     { if(nBig++==0) arg1=p; else arg2=p; }   // 131072
        else if(sz == 2*Dn*Kn)      { if(nMed++==0) Wd=p;   else Wg=p; }     // 16384
        else if(sz == Kn)           { if(nSmall==0) bg=p; else if(nSmall==1) bb=p; else u=p; nSmall++; }
    }
    float* out = (float*)d_out;

    static int attr_done = 0;
    if(!attr_done){
        cudaFuncSetAttribute(fused_kernel, cudaFuncAttributeMaxDynamicSharedMemorySize, FUSED_SMEM_FLOATS*4);
        attr_done = 1;
    }

    fused_kernel<<<Bn*Kn,256, FUSED_SMEM_FLOATS*4>>>(arg1, arg2, Wb, Wd, Wg, bg, bb, u);
    reduce_kernel<<<128,256>>>(out);
}

// round 12
// speedup vs baseline: 3.5346x; 1.2532x over previous
#include <cuda_runtime.h>
#include <cuda_bf16.h>
#include <math.h>
#include <stdint.h>

#define Bn 8
#define Ln 64
#define Dn 256
#define Kn 32

// Scratch (device globals -- allocation is forbidden)
__device__ float g_S[Bn*Kn*Ln*Ln];             // 4 MB per-k scaled contributions
__device__ unsigned short g_Wbh[Kn*Dn*Dn];     // bf16 hi split of Wb  [k][e][f]
__device__ unsigned short g_Wbl[Kn*Dn*Dn];     // bf16 lo split
__device__ unsigned short g_A1h[Bn*Ln*Dn];     // bf16 hi split of arg1 [b][m][e]
__device__ unsigned short g_A1l[Bn*Ln*Dn];

// ---- packed f32x2 helpers ----
__device__ __forceinline__ uint64_t pack2(float x, float y){
    uint64_t r; asm("mov.b64 %0, {%1,%2};" : "=l"(r) : "f"(x), "f"(y)); return r;
}
__device__ __forceinline__ uint64_t fma2(uint64_t a, uint64_t b, uint64_t c){
    uint64_t d; asm("fma.rn.f32x2 %0, %1, %2, %3;" : "=l"(d) : "l"(a), "l"(b), "l"(c)); return d;
}
__device__ __forceinline__ void unpack2(uint64_t v, float& x, float& y){
    asm("mov.b64 {%0,%1}, %2;" : "=f"(x), "=f"(y) : "l"(v));
}
// ---- cp.async ----
__device__ __forceinline__ void cp16(uint32_t dst, const void* src){
    asm volatile("cp.async.cg.shared.global [%0], [%1], 16;" :: "r"(dst), "l"(src));
}
#define CP_COMMIT() asm volatile("cp.async.commit_group;")
#define CP_WAIT0()  asm volatile("cp.async.wait_group 0;")
#define CP_WAIT1()  asm volatile("cp.async.wait_group 1;")
// ---- mma.sync / ldmatrix (family-safe: sm_80-era instructions) ----
__device__ __forceinline__ void ldsm_x4(uint32_t* r, uint32_t addr){
    asm volatile("ldmatrix.sync.aligned.m8n8.x4.shared.b16 {%0,%1,%2,%3}, [%4];"
        : "=r"(r[0]),"=r"(r[1]),"=r"(r[2]),"=r"(r[3]) : "r"(addr));
}
__device__ __forceinline__ void ldsm_x2t(uint32_t& r0, uint32_t& r1, uint32_t addr){
    asm volatile("ldmatrix.sync.aligned.m8n8.x2.trans.shared.b16 {%0,%1}, [%2];"
        : "=r"(r0), "=r"(r1) : "r"(addr));
}
__device__ __forceinline__ void mma_bf16(float* c, const uint32_t* a, uint32_t b0, uint32_t b1){
    asm volatile("mma.sync.aligned.m16n8k16.row.col.f32.bf16.bf16.f32 "
        "{%0,%1,%2,%3}, {%4,%5,%6,%7}, {%8,%9}, {%0,%1,%2,%3};"
        : "+f"(c[0]), "+f"(c[1]), "+f"(c[2]), "+f"(c[3])
        : "r"(a[0]), "r"(a[1]), "r"(a[2]), "r"(a[3]), "r"(b0), "r"(b1));
}
__device__ __forceinline__ uint32_t smem_u32_of(const void* p){
    uint32_t a;
    asm("{ .reg .u64 t; cvta.to.shared.u64 t, %1; cvt.u32.u64 %0, t; }" : "=r"(a) : "l"(p));
    return a;
}
__device__ __forceinline__ void bf16split4(float4 v, uint2& hv, uint2& lv){
    __nv_bfloat16 h0=__float2bfloat16(v.x), h1=__float2bfloat16(v.y);
    __nv_bfloat16 h2=__float2bfloat16(v.z), h3=__float2bfloat16(v.w);
    __nv_bfloat16 l0=__float2bfloat16(v.x-__bfloat162float(h0));
    __nv_bfloat16 l1=__float2bfloat16(v.y-__bfloat162float(h1));
    __nv_bfloat16 l2=__float2bfloat16(v.z-__bfloat162float(h2));
    __nv_bfloat16 l3=__float2bfloat16(v.w-__bfloat162float(h3));
    hv.x = (uint32_t)__bfloat16_as_ushort(h0) | ((uint32_t)__bfloat16_as_ushort(h1)<<16);
    hv.y = (uint32_t)__bfloat16_as_ushort(h2) | ((uint32_t)__bfloat16_as_ushort(h3)<<16);
    lv.x = (uint32_t)__bfloat16_as_ushort(l0) | ((uint32_t)__bfloat16_as_ushort(l1)<<16);
    lv.y = (uint32_t)__bfloat16_as_ushort(l2) | ((uint32_t)__bfloat16_as_ushort(l3)<<16);
}

// ---- K0: bf16 hi/lo split of Wb and arg1 ----
__global__ void prep_kernel(const float* __restrict__ Wb, const float* __restrict__ arg1){
    int idx = blockIdx.x*blockDim.x + threadIdx.x;   // float4 units
    const int nW = Kn*Dn*Dn/4;                       // 524288
    const int nA = Bn*Ln*Dn/4;                       // 32768
    if(idx < nW){
        uint2 hv, lv;
        bf16split4(((const float4*)Wb)[idx], hv, lv);
        ((uint2*)g_Wbh)[idx] = hv;
        ((uint2*)g_Wbl)[idx] = lv;
    } else if(idx < nW + nA){
        int j = idx - nW;
        uint2 hv, lv;
        bf16split4(((const float4*)arg1)[j], hv, lv);
        ((uint2*)g_A1h)[j] = hv;
        ((uint2*)g_A1l)[j] = lv;
    }
}

// ===================== fused kernel ==========================================
// block = (b,k). Phase 1: T = arg1[b] @ Wb[k] via bf16 mma.sync, 3-pass split,
// fp32 accum in frags. Phase 2 + epilogue: verified SIMT f32x2 code.
// smem (bytes):
//   phase-1: AH @0 (64 rows x 528B = 33792); AL @33792;
//            WH 2x(16x528=8448) @67584; WL 2x8448 @84480  -> end 101376
//   phase-2 overlay: T_sh f32 [64][130] @0 (33280); A2t f32 [128][132] @33280 -> end 100864
//   tails:   P2 (512 f32) @101376; Wcol (1024 f32) @103424 -> total 107520 B
#define AH_B 0
#define AL_B 33792
#define WH_B 67584
#define WL_B 84480
#define P2_F 25344
#define WCOL_F 25856
#define A2T_F 8320
#define PAD2 130
#define PADT2 132
#define SMEM_BYTES 107520
__global__ void __launch_bounds__(256,2) fused_kernel(
        const float* __restrict__ arg1, const float* __restrict__ arg2,
        const float* __restrict__ Wd, const float* __restrict__ Wg,
        const float* __restrict__ bgp, const float* __restrict__ bp,
        const float* __restrict__ up){
    extern __shared__ float sh[];
    float* T_sh = sh;                      // [64][130] (phase-2 overlay)
    float* A2t  = sh + A2T_F;              // [128][132]
    float* P2   = sh + P2_F;               // a1d[64] a1g[64] a2part[256]
    float* Wcol = sh + WCOL_F;             // [4][256]

    int b = blockIdx.x >> 5, k = blockIdx.x & 31;
    int tid = threadIdx.x;
    int wid = tid >> 5, lane = tid & 31;
    int wm = wid & 3, wf = wid >> 2;       // warp tile: m0 = 16*wm, f-half = wf
    int m0 = 16*wm;
    uint32_t smem0 = smem_u32_of(sh);

    // ---- Wcol (Wd/Wg columns for this k) ----
    for(int i = tid; i < 4*Dn; i += 256){
        int arr = i >> 8, e = i & 255;
        float v;
        if(arr==0)      v = Wd[e*Kn + k];
        else if(arr==1) v = Wg[e*Kn + k];
        else if(arr==2) v = Wd[(Dn+e)*Kn + k];
        else            v = Wg[(Dn+e)*Kn + k];
        Wcol[i] = v;
    }

    // ---- cp.async: A (hi/lo, all 256 e) + W chunk 0 ----
    const char* a1hB = (const char*)g_A1h + (size_t)(b*Ln)*Dn*2;
    const char* a1lB = (const char*)g_A1l + (size_t)(b*Ln)*Dn*2;
    #pragma unroll
    for(int r = 0; r < 8; r++){
        int idx = tid + 256*r;             // 0..2047
        int m = idx >> 5, ch = idx & 31;
        cp16(smem0 + AH_B + m*528 + ch*16, a1hB + m*512 + ch*16);
        cp16(smem0 + AL_B + m*528 + ch*16, a1lB + m*512 + ch*16);
    }
    const char* wkhB = (const char*)g_Wbh + (size_t)k*Dn*Dn*2;
    const char* wklB = (const char*)g_Wbl + (size_t)k*Dn*Dn*2;
    #pragma unroll
    for(int r = 0; r < 2; r++){
        int idx = tid + 256*r;             // 0..511
        int row = idx >> 5, ch = idx & 31;
        cp16(smem0 + WH_B + row*528 + ch*16, wkhB + row*512 + ch*16);
        cp16(smem0 + WL_B + row*528 + ch*16, wklB + row*512 + ch*16);
    }
    CP_COMMIT();

    // ---------- phase 1: 16 ksteps of 16e, double-buffered ----------
    float acc[16][4];                      // [ntile][c-frag]; f = wf*128 + nt*8 + {2tig,2tig+1} x {g, g+8}
    #pragma unroll
    for(int nt = 0; nt < 16; nt++)
        #pragma unroll
        for(int q = 0; q < 4; q++) acc[nt][q] = 0.f;

    uint32_t aBaseH = smem0 + AH_B + (m0 + (lane & 15))*528;
    uint32_t aBaseL = smem0 + AL_B + (m0 + (lane & 15))*528;
    uint32_t wRow   = (lane & 15)*528 + wf*256;   // + buffer base + nt*16

    for(int c = 0; c < 16; c++){
        int bi = c & 1;
        if(c < 15){
            int bj = (c+1) & 1, e16 = (c+1)*16;
            #pragma unroll
            for(int r = 0; r < 2; r++){
                int idx = tid + 256*r;
                int row = idx >> 5, ch = idx & 31;
                cp16(smem0 + WH_B + bj*8448 + row*528 + ch*16, wkhB + (e16+row)*512 + ch*16);
                cp16(smem0 + WL_B + bj*8448 + row*528 + ch*16, wklB + (e16+row)*512 + ch*16);
            }
            CP_COMMIT();
            CP_WAIT1();
        } else {
            CP_WAIT0();
        }
        __syncthreads();                   // chunk c visible to all

        uint32_t cofs = (uint32_t)(c*32 + ((lane >> 4)*16));
        uint32_t ah[4], al[4];
        ldsm_x4(ah, aBaseH + cofs);
        ldsm_x4(al, aBaseL + cofs);
        uint32_t wH = smem0 + WH_B + bi*8448 + wRow;
        uint32_t wL = smem0 + WL_B + bi*8448 + wRow;
        #pragma unroll
        for(int nt = 0; nt < 16; nt++){
            uint32_t bh0, bh1, bl0, bl1;
            ldsm_x2t(bh0, bh1, wH + nt*16);
            ldsm_x2t(bl0, bl1, wL + nt*16);
            mma_bf16(acc[nt], ah, bh0, bh1);   // hi*hi
            mma_bf16(acc[nt], al, bh0, bh1);   // lo*hi
            mma_bf16(acc[nt], ah, bl0, bl1);   // hi*lo
        }
        __syncthreads();                   // all reads done before next prefetch lands
    }

    // ---- a1d/a1g dots: warp-per-dot-group, coalesced gmem + shfl reduce ----
    {
        #pragma unroll 1
        for(int j = 0; j < 16; j++){
            int dd = wid*16 + j;           // 0..127
            int arr = dd >> 6, m = dd & 63;
            const float* row = arg1 + (b*Ln + m)*Dn;
            float s = 0.f;
            #pragma unroll
            for(int t = 0; t < 8; t++){
                int e = lane + 32*t;
                s = fmaf(row[e], Wcol[arr*Dn + e], s);
            }
            #pragma unroll
            for(int off = 16; off; off >>= 1) s += __shfl_xor_sync(0xFFFFFFFFu, s, off);
            if(lane == 0) P2[arr*64 + m] = s;
        }
    }

    // ---------- phase 2: btp = T @ arg2^T (verified SIMT f32x2) ----------
    const float* A2 = arg2 + b*Ln*Dn;
    int tx = tid & 15, ty = tid >> 4;      // m = 4*ty+i, n = 4*tx+jj
    uint64_t bacc[4][2];
    #pragma unroll
    for(int i = 0; i < 4; i++){ bacc[i][0] = pack2(0.f,0.f); bacc[i][1] = pack2(0.f,0.f); }
    float s2 = 0.f;

    for(int c2 = 0; c2 < 2; c2++){
        __syncthreads();                   // prior chunk reads done / phase-1 smem free
        if(wf == c2){
            // spill this half's T frags to T_sh[m][f_local]
            int g = lane >> 2, tg = lane & 3;
            #pragma unroll
            for(int nt = 0; nt < 16; nt++){
                int fl = nt*8 + 2*tg;
                float2 v01; v01.x = acc[nt][0]; v01.y = acc[nt][1];
                float2 v23; v23.x = acc[nt][2]; v23.y = acc[nt][3];
                *(float2*)&T_sh[(m0+g)*PAD2 + fl]   = v01;   // even offsets, 8B aligned
                *(float2*)&T_sh[(m0+g+8)*PAD2 + fl] = v23;
            }
        } else {
            // other 128 threads stage arg2 chunk transposed
            int lt = tid & 127;
            for(int i = lt; i < 128*128; i += 128){
                int r = i >> 7, cc = i & 127;
                A2t[cc*PADT2 + r] = A2[r*Dn + c2*128 + cc];
            }
        }
        __syncthreads();
        #pragma unroll 4
        for(int f = 0; f < 128; f++){
            float4 av4 = *(const float4*)(A2t + f*PADT2 + 4*tx);
            uint64_t avp0 = pack2(av4.x, av4.y);
            uint64_t avp1 = pack2(av4.z, av4.w);
            #pragma unroll
            for(int i = 0; i < 4; i++){
                float t = T_sh[(4*ty+i)*PAD2 + f];
                uint64_t tp = pack2(t, t);
                bacc[i][0] = fma2(tp, avp0, bacc[i][0]);
                bacc[i][1] = fma2(tp, avp1, bacc[i][1]);
            }
        }
        // a2d/a2g partial dots from staged chunk (all 256 threads, half-f each)
        {
            int n = tid & 63, arr = (tid >> 6) & 1, half = tid >> 7;
            int f0 = half*64;
            #pragma unroll 8
            for(int f = f0; f < f0+64; f++)
                s2 = fmaf(A2t[f*PADT2 + n], Wcol[(2+arr)*Dn + c2*128 + f], s2);
        }
    }
    {
        int n = tid & 63, arr = (tid >> 6) & 1, half = tid >> 7;
        P2[128 + half*128 + arr*64 + n] = s2;
    }
    __syncthreads();                       // P2 complete

    // ---------- epilogue (verified) ----------
    float bgk = bgp[k], bk = bp[k], uk = up[k];
    float a2d_v[4], a2g_v[4];
    #pragma unroll
    for(int jj = 0; jj < 4; jj++){
        int n = 4*tx + jj;
        a2d_v[jj] = P2[128 + n] + P2[256 + n];
        a2g_v[jj] = P2[192 + n] + P2[320 + n];
    }
    float* Sb = g_S + (size_t)(b*Kn + k)*Ln*Ln;
    #pragma unroll
    for(int i = 0; i < 4; i++){
        int m = 4*ty + i;
        float a1d_v = P2[m];
        float a1g_v = P2[64 + m];
        float av[4];
        unpack2(bacc[i][0], av[0], av[1]);
        unpack2(bacc[i][1], av[2], av[3]);
        float r[4];
        #pragma unroll
        for(int jj = 0; jj < 4; jj++){
            float sln = tanhf(a1d_v + a2d_v[jj]);
            float xg  = a1g_v + a2g_v[jj] + bgk;
            float gt  = 1.0f/(1.0f + expf(-xg));
            r[jj] = uk*(gt*av[jj] + (1.0f-gt)*sln + bk);
        }
        float4 outv; outv.x=r[0]; outv.y=r[1]; outv.z=r[2]; outv.w=r[3];
        *(float4*)(Sb + m*Ln + 4*tx) = outv;
    }
}

// ---- deterministic k-reduction (scalar, grid 128 — measured fastest) ----
__global__ void reduce_kernel(float* __restrict__ out){
    int idx = blockIdx.x*blockDim.x + threadIdx.x;   // 32768
    int b = idx >> 12, mn = idx & 4095;
    const float* s = g_S + (size_t)b*Kn*4096 + mn;
    float acc = 0.f;
    #pragma unroll
    for(int kk = 0; kk < Kn; kk++) acc += s[kk*4096];
    out[idx] = acc;
}

extern "C" void kernel_launch(void* const* d_in, const int* in_sizes, int n_in,
                              void* d_out, int out_size){
    const float *arg1=0,*arg2=0,*Wb=0,*Wd=0,*Wg=0,*bg=0,*bb=0,*u=0;
    int nBig=0, nMed=0, nSmall=0;
    for(int i=0;i<n_in;i++){
        int sz = in_sizes[i];
        const float* pp = (const float*)d_in[i];
        if(sz == Kn*Dn*Dn)          Wb = pp;
        else if(sz == Bn*Ln*Dn)     { if(nBig++==0) arg1=pp; else arg2=pp; }
        else if(sz == 2*Dn*Kn)      { if(nMed++==0) Wd=pp;   else Wg=pp; }
        else if(sz == Kn)           { if(nSmall==0) bg=pp; else if(nSmall==1) bb=pp; else u=pp; nSmall++; }
    }
    float* out = (float*)d_out;

    static int attr_done = 0;
    if(!attr_done){
        cudaFuncSetAttribute(fused_kernel, cudaFuncAttributeMaxDynamicSharedMemorySize, SMEM_BYTES);
        attr_done = 1;
    }

    prep_kernel <<<2176, 256>>>(Wb, arg1);
    fused_kernel<<<Bn*Kn, 256, SMEM_BYTES>>>(arg1, arg2, Wd, Wg, bg, bb, u);
    reduce_kernel<<<128, 256>>>(out);
}

// round 13
// speedup vs baseline: 4.6568x; 1.3175x over previous
#include <cuda_runtime.h>
#include <cuda_bf16.h>
#include <math.h>
#include <stdint.h>

#define Bn 8
#define Ln 64
#define Dn 256
#define Kn 32

// Scratch (device globals -- allocation is forbidden)
__device__ float g_S[Bn*Kn*Ln*Ln];             // 4 MB per-k scaled contributions
__device__ unsigned short g_Wbh[Kn*Dn*Dn];     // bf16 hi split of Wb  [k][e][f]
__device__ unsigned short g_Wbl[Kn*Dn*Dn];
__device__ unsigned short g_A1h[Bn*Ln*Dn];     // bf16 hi split of arg1 [b][m][e]
__device__ unsigned short g_A1l[Bn*Ln*Dn];
__device__ unsigned short g_A2h[Bn*Ln*Dn];     // bf16 hi split of arg2 [b][n][f]
__device__ unsigned short g_A2l[Bn*Ln*Dn];

// ---- cp.async ----
__device__ __forceinline__ void cp16(uint32_t dst, const void* src){
    asm volatile("cp.async.cg.shared.global [%0], [%1], 16;" :: "r"(dst), "l"(src));
}
#define CP_COMMIT() asm volatile("cp.async.commit_group;")
#define CP_WAIT0()  asm volatile("cp.async.wait_group 0;")
#define CP_WAIT1()  asm volatile("cp.async.wait_group 1;")
// ---- mma.sync / ldmatrix (family-safe) ----
__device__ __forceinline__ void ldsm_x4(uint32_t* r, uint32_t addr){
    asm volatile("ldmatrix.sync.aligned.m8n8.x4.shared.b16 {%0,%1,%2,%3}, [%4];"
        : "=r"(r[0]),"=r"(r[1]),"=r"(r[2]),"=r"(r[3]) : "r"(addr));
}
__device__ __forceinline__ void ldsm_x2t(uint32_t& r0, uint32_t& r1, uint32_t addr){
    asm volatile("ldmatrix.sync.aligned.m8n8.x2.trans.shared.b16 {%0,%1}, [%2];"
        : "=r"(r0), "=r"(r1) : "r"(addr));
}
__device__ __forceinline__ void mma_bf16(float* c, const uint32_t* a, uint32_t b0, uint32_t b1){
    asm volatile("mma.sync.aligned.m16n8k16.row.col.f32.bf16.bf16.f32 "
        "{%0,%1,%2,%3}, {%4,%5,%6,%7}, {%8,%9}, {%0,%1,%2,%3};"
        : "+f"(c[0]), "+f"(c[1]), "+f"(c[2]), "+f"(c[3])
        : "r"(a[0]), "r"(a[1]), "r"(a[2]), "r"(a[3]), "r"(b0), "r"(b1));
}
__device__ __forceinline__ uint32_t smem_u32_of(const void* p){
    uint32_t a;
    asm("{ .reg .u64 t; cvta.to.shared.u64 t, %1; cvt.u32.u64 %0, t; }" : "=r"(a) : "l"(p));
    return a;
}
__device__ __forceinline__ void bf16split4(float4 v, uint2& hv, uint2& lv){
    __nv_bfloat16 h0=__float2bfloat16(v.x), h1=__float2bfloat16(v.y);
    __nv_bfloat16 h2=__float2bfloat16(v.z), h3=__float2bfloat16(v.w);
    __nv_bfloat16 l0=__float2bfloat16(v.x-__bfloat162float(h0));
    __nv_bfloat16 l1=__float2bfloat16(v.y-__bfloat162float(h1));
    __nv_bfloat16 l2=__float2bfloat16(v.z-__bfloat162float(h2));
    __nv_bfloat16 l3=__float2bfloat16(v.w-__bfloat162float(h3));
    hv.x = (uint32_t)__bfloat16_as_ushort(h0) | ((uint32_t)__bfloat16_as_ushort(h1)<<16);
    hv.y = (uint32_t)__bfloat16_as_ushort(h2) | ((uint32_t)__bfloat16_as_ushort(h3)<<16);
    lv.x = (uint32_t)__bfloat16_as_ushort(l0) | ((uint32_t)__bfloat16_as_ushort(l1)<<16);
    lv.y = (uint32_t)__bfloat16_as_ushort(l2) | ((uint32_t)__bfloat16_as_ushort(l3)<<16);
}
// split one fp32 pair into packed bf16 hi + lo regs
__device__ __forceinline__ void split_pair(float x, float y, uint32_t& h, uint32_t& l){
    __nv_bfloat16 hx=__float2bfloat16(x), hy=__float2bfloat16(y);
    __nv_bfloat16 lx=__float2bfloat16(x-__bfloat162float(hx));
    __nv_bfloat16 ly=__float2bfloat16(y-__bfloat162float(hy));
    h = (uint32_t)__bfloat16_as_ushort(hx) | ((uint32_t)__bfloat16_as_ushort(hy)<<16);
    l = (uint32_t)__bfloat16_as_ushort(lx) | ((uint32_t)__bfloat16_as_ushort(ly)<<16);
}

// ---- K0: bf16 hi/lo split of Wb, arg1, arg2 ----
__global__ void prep_kernel(const float* __restrict__ Wb, const float* __restrict__ arg1,
                            const float* __restrict__ arg2){
    int idx = blockIdx.x*blockDim.x + threadIdx.x;   // float4 units
    const int nW = Kn*Dn*Dn/4;                       // 524288
    const int nA = Bn*Ln*Dn/4;                       // 32768
    if(idx < nW){
        uint2 hv, lv;
        bf16split4(((const float4*)Wb)[idx], hv, lv);
        ((uint2*)g_Wbh)[idx] = hv;  ((uint2*)g_Wbl)[idx] = lv;
    } else if(idx < nW + nA){
        int j = idx - nW;
        uint2 hv, lv;
        bf16split4(((const float4*)arg1)[j], hv, lv);
        ((uint2*)g_A1h)[j] = hv;  ((uint2*)g_A1l)[j] = lv;
    } else if(idx < nW + 2*nA){
        int j = idx - nW - nA;
        uint2 hv, lv;
        bf16split4(((const float4*)arg2)[j], hv, lv);
        ((uint2*)g_A2h)[j] = hv;  ((uint2*)g_A2l)[j] = lv;
    }
}

// ===================== fused kernel ==========================================
// block = (b,k).  Phase 1 (verified): T = arg1[b]@Wb[k] bf16 mma 3-pass, frags.
// Phase 2 (new): btp = T@arg2^T via mma; A-frags straight from phase-1 C-frags
// (identical register layout), B-frags = 2x LDS.32 from bf16 arg2 [n][f] rows.
// smem (bytes):
//   phase-1: AH @0 (64x528=33792); AL @33792; WH 2x8448 @67584; WL @84480 ->101376
//   phase-2 overlay: A2H @0 (33792); A2L @33792; PC f32 [64][72] @67584 (18432)
//   tails:   P2 (256 f32) @101376; Wcol (1024 f32) @102400 -> total 106496 B
#define AH_B 0
#define AL_B 33792
#define WH_B 67584
#define WL_B 84480
#define A2H_B 0
#define A2L_B 33792
#define PC_F 16896
#define PCS 72
#define P2_F 25344
#define WCOL_F 25600
#define SMEM_BYTES 106496
__global__ void __launch_bounds__(256,2) fused_kernel(
        const float* __restrict__ arg1, const float* __restrict__ arg2,
        const float* __restrict__ Wd, const float* __restrict__ Wg,
        const float* __restrict__ bgp, const float* __restrict__ bp,
        const float* __restrict__ up){
    extern __shared__ float sh[];
    float* PC   = sh + PC_F;               // [64][72] cross-warp C partials
    float* P2   = sh + P2_F;               // a1d[64] a1g[64] a2d[64] a2g[64]
    float* Wcol = sh + WCOL_F;              // [4][256]

    int b = blockIdx.x >> 5, k = blockIdx.x & 31;
    int tid = threadIdx.x;
    int wid = tid >> 5, lane = tid & 31;
    int wm = wid & 3, wf = wid >> 2;        // warp tile: m0 = 16*wm, f-half wf
    int m0 = 16*wm;
    int g = lane >> 2, tg = lane & 3;
    uint32_t smem0 = smem_u32_of(sh);

    // ---- Wcol (Wd/Wg columns for this k) ----
    for(int i = tid; i < 4*Dn; i += 256){
        int arr = i >> 8, e = i & 255;
        float v;
        if(arr==0)      v = Wd[e*Kn + k];
        else if(arr==1) v = Wg[e*Kn + k];
        else if(arr==2) v = Wd[(Dn+e)*Kn + k];
        else            v = Wg[(Dn+e)*Kn + k];
        Wcol[i] = v;
    }

    // ---- cp.async: A1 (hi/lo) + W chunk 0 ----
    const char* a1hB = (const char*)g_A1h + (size_t)(b*Ln)*Dn*2;
    const char* a1lB = (const char*)g_A1l + (size_t)(b*Ln)*Dn*2;
    #pragma unroll
    for(int r = 0; r < 8; r++){
        int idx = tid + 256*r;              // 0..2047
        int m = idx >> 5, ch = idx & 31;
        cp16(smem0 + AH_B + m*528 + ch*16, a1hB + m*512 + ch*16);
        cp16(smem0 + AL_B + m*528 + ch*16, a1lB + m*512 + ch*16);
    }
    const char* wkhB = (const char*)g_Wbh + (size_t)k*Dn*Dn*2;
    const char* wklB = (const char*)g_Wbl + (size_t)k*Dn*Dn*2;
    #pragma unroll
    for(int r = 0; r < 2; r++){
        int idx = tid + 256*r;
        int row = idx >> 5, ch = idx & 31;
        cp16(smem0 + WH_B + row*528 + ch*16, wkhB + row*512 + ch*16);
        cp16(smem0 + WL_B + row*528 + ch*16, wklB + row*512 + ch*16);
    }
    CP_COMMIT();

    // ---------- phase 1 (verified): 16 ksteps of 16e, double-buffered ----------
    float acc[16][4];
    #pragma unroll
    for(int nt = 0; nt < 16; nt++)
        #pragma unroll
        for(int q = 0; q < 4; q++) acc[nt][q] = 0.f;

    uint32_t aBaseH = smem0 + AH_B + (m0 + (lane & 15))*528;
    uint32_t aBaseL = smem0 + AL_B + (m0 + (lane & 15))*528;
    uint32_t wRow   = (lane & 15)*528 + wf*256;

    for(int c = 0; c < 16; c++){
        int bi = c & 1;
        if(c < 15){
            int bj = (c+1) & 1, e16 = (c+1)*16;
            #pragma unroll
            for(int r = 0; r < 2; r++){
                int idx = tid + 256*r;
                int row = idx >> 5, ch = idx & 31;
                cp16(smem0 + WH_B + bj*8448 + row*528 + ch*16, wkhB + (e16+row)*512 + ch*16);
                cp16(smem0 + WL_B + bj*8448 + row*528 + ch*16, wklB + (e16+row)*512 + ch*16);
            }
            CP_COMMIT();
            CP_WAIT1();
        } else {
            CP_WAIT0();
        }
        __syncthreads();

        uint32_t cofs = (uint32_t)(c*32 + ((lane >> 4)*16));
        uint32_t ah[4], al[4];
        ldsm_x4(ah, aBaseH + cofs);
        ldsm_x4(al, aBaseL + cofs);
        uint32_t wH = smem0 + WH_B + bi*8448 + wRow;
        uint32_t wL = smem0 + WL_B + bi*8448 + wRow;
        #pragma unroll
        for(int nt = 0; nt < 16; nt++){
            uint32_t bh0, bh1, bl0, bl1;
            ldsm_x2t(bh0, bh1, wH + nt*16);
            ldsm_x2t(bl0, bl1, wL + nt*16);
            mma_bf16(acc[nt], ah, bh0, bh1);
            mma_bf16(acc[nt], al, bh0, bh1);
            mma_bf16(acc[nt], ah, bl0, bl1);
        }
        __syncthreads();
    }

    // ---- cp.async: arg2 bf16 hi/lo into freed A region ----
    const char* a2hB = (const char*)g_A2h + (size_t)(b*Ln)*Dn*2;
    const char* a2lB = (const char*)g_A2l + (size_t)(b*Ln)*Dn*2;
    #pragma unroll
    for(int r = 0; r < 8; r++){
        int idx = tid + 256*r;
        int n = idx >> 5, ch = idx & 31;
        cp16(smem0 + A2H_B + n*528 + ch*16, a2hB + n*512 + ch*16);
        cp16(smem0 + A2L_B + n*528 + ch*16, a2lB + n*512 + ch*16);
    }
    CP_COMMIT();

    // ---- projections: 256 warp-dots (fp32, gmem rows are L2-hot) ----
    {
        #pragma unroll 1
        for(int j = 0; j < 32; j++){
            int dd = wid*32 + j;            // 0..255
            int arr = dd >> 6, m = dd & 63; // 0:a1d 1:a1g 2:a2d 3:a2g
            const float* row = ((arr < 2) ? arg1 : arg2) + (b*Ln + m)*Dn;
            float s = 0.f;
            #pragma unroll
            for(int t = 0; t < 8; t++){
                int e = lane + 32*t;
                s = fmaf(row[e], Wcol[arr*Dn + e], s);
            }
            #pragma unroll
            for(int off = 16; off; off >>= 1) s += __shfl_xor_sync(0xFFFFFFFFu, s, off);
            if(lane == 0) P2[dd] = s;
        }
    }
    CP_WAIT0();
    __syncthreads();                        // A2 tiles + P2 visible

    // ---------- phase 2: btp = T @ arg2^T via mma ----------
    // warp covers C tile m16 (m0) x n64, K = its f-half (8 kchunks of 16).
    float C[8][4];
    #pragma unroll
    for(int nt = 0; nt < 8; nt++)
        #pragma unroll
        for(int q = 0; q < 4; q++) C[nt][q] = 0.f;

    const char* smc = (const char*)sh;
    #pragma unroll
    for(int kc = 0; kc < 8; kc++){
        // A-frags from acc (C-frag layout == A-frag layout)
        uint32_t ah[4], al[4];
        split_pair(acc[2*kc][0],   acc[2*kc][1],   ah[0], al[0]);
        split_pair(acc[2*kc][2],   acc[2*kc][3],   ah[1], al[1]);
        split_pair(acc[2*kc+1][0], acc[2*kc+1][1], ah[2], al[2]);
        split_pair(acc[2*kc+1][2], acc[2*kc+1][3], ah[3], al[3]);
        int fbyte = wf*256 + kc*32 + tg*4;  // byte offset of k=2tg within row
        #pragma unroll
        for(int nt = 0; nt < 8; nt++){
            int rowb = (8*nt + g)*528 + fbyte;
            uint32_t bh0 = *(const uint32_t*)(smc + A2H_B + rowb);
            uint32_t bh1 = *(const uint32_t*)(smc + A2H_B + rowb + 16);
            uint32_t bl0 = *(const uint32_t*)(smc + A2L_B + rowb);
            uint32_t bl1 = *(const uint32_t*)(smc + A2L_B + rowb + 16);
            mma_bf16(C[nt], ah, bh0, bh1);
            mma_bf16(C[nt], al, bh0, bh1);
            mma_bf16(C[nt], ah, bl0, bl1);
        }
    }

    // ---- cross-warp combine (wf=0 writes, wf=1 adds) ----
    if(wf == 0){
        #pragma unroll
        for(int nt = 0; nt < 8; nt++){
            int col = 8*nt + 2*tg;
            *(float2*)&PC[(m0+g)*PCS + col]   = make_float2(C[nt][0], C[nt][1]);
            *(float2*)&PC[(m0+g+8)*PCS + col] = make_float2(C[nt][2], C[nt][3]);
        }
    }
    __syncthreads();

    if(wf == 1){
        float bgk = bgp[k], bk = bp[k], uk = up[k];
        float* Sb = g_S + (size_t)(b*Kn + k)*Ln*Ln;
        float a1d0 = P2[m0+g],      a1g0 = P2[64+m0+g];
        float a1d1 = P2[m0+g+8],    a1g1 = P2[64+m0+g+8];
        #pragma unroll
        for(int nt = 0; nt < 8; nt++){
            int col = 8*nt + 2*tg;
            float2 p0 = *(float2*)&PC[(m0+g)*PCS + col];
            float2 p1 = *(float2*)&PC[(m0+g+8)*PCS + col];
            float v00 = C[nt][0] + p0.x, v01 = C[nt][1] + p0.y;
            float v10 = C[nt][2] + p1.x, v11 = C[nt][3] + p1.y;
            float a2d0 = P2[128+col], a2d1 = P2[128+col+1];
            float a2g0 = P2[192+col], a2g1 = P2[192+col+1];
            float r00, r01, r10, r11;
            {
                float sln = tanhf(a1d0 + a2d0);
                float gt  = 1.0f/(1.0f + expf(-(a1g0 + a2g0 + bgk)));
                r00 = uk*(gt*v00 + (1.0f-gt)*sln + bk);
                sln = tanhf(a1d0 + a2d1);
                gt  = 1.0f/(1.0f + expf(-(a1g0 + a2g1 + bgk)));
                r01 = uk*(gt*v01 + (1.0f-gt)*sln + bk);
                sln = tanhf(a1d1 + a2d0);
                gt  = 1.0f/(1.0f + expf(-(a1g1 + a2g0 + bgk)));
                r10 = uk*(gt*v10 + (1.0f-gt)*sln + bk);
                sln = tanhf(a1d1 + a2d1);
                gt  = 1.0f/(1.0f + expf(-(a1g1 + a2g1 + bgk)));
                r11 = uk*(gt*v11 + (1.0f-gt)*sln + bk);
            }
            *(float2*)&Sb[(m0+g)*Ln + col]   = make_float2(r00, r01);
            *(float2*)&Sb[(m0+g+8)*Ln + col] = make_float2(r10, r11);
        }
    }
}

// ---- deterministic k-reduction ----
__global__ void reduce_kernel(float* __restrict__ out){
    int idx = blockIdx.x*blockDim.x + threadIdx.x;   // 32768
    int b = idx >> 12, mn = idx & 4095;
    const float* s = g_S + (size_t)b*Kn*4096 + mn;
    float acc = 0.f;
    #pragma unroll
    for(int kk = 0; kk < Kn; kk++) acc += s[kk*4096];
    out[idx] = acc;
}

extern "C" void kernel_launch(void* const* d_in, const int* in_sizes, int n_in,
                              void* d_out, int out_size){
    const float *arg1=0,*arg2=0,*Wb=0,*Wd=0,*Wg=0,*bg=0,*bb=0,*u=0;
    int nBig=0, nMed=0, nSmall=0;
    for(int i=0;i<n_in;i++){
        int sz = in_sizes[i];
        const float* pp = (const float*)d_in[i];
        if(sz == Kn*Dn*Dn)          Wb = pp;
        else if(sz == Bn*Ln*Dn)     { if(nBig++==0) arg1=pp; else arg2=pp; }
        else if(sz == 2*Dn*Kn)      { if(nMed++==0) Wd=pp;   else Wg=pp; }
        else if(sz == Kn)           { if(nSmall==0) bg=pp; else if(nSmall==1) bb=pp; else u=pp; nSmall++; }
    }
    float* out = (float*)d_out;

    static int attr_done = 0;
    if(!attr_done){
        cudaFuncSetAttribute(fused_kernel, cudaFuncAttributeMaxDynamicSharedMemorySize, SMEM_BYTES);
        attr_done = 1;
    }

    prep_kernel <<<2304, 256>>>(Wb, arg1, arg2);
    fused_kernel<<<Bn*Kn, 256, SMEM_BYTES>>>(arg1, arg2, Wd, Wg, bg, bb, u);
    reduce_kernel<<<128, 256>>>(out);
}